// round 2
// baseline (speedup 1.0000x reference)
#include <cuda_runtime.h>
#include <math.h>
#include <stddef.h>

// ---------------- problem constants ----------------
#define B_   32
#define S_   197
#define D_   768
#define L_   12
#define FF_  3072
#define NH_  12
#define HD_  64
#define NC_  1000
#define NP_  196          // patches per image
#define MTOK (B_ * S_)    // 6304 tokens
#define MPAT (B_ * NP_)   // 6272 patch rows
#define BH_  (B_ * NH_)   // 384 attention matrices

// ---------------- scratch (static device globals; no allocs allowed) ----------------
__device__ float g_A   [(size_t)MPAT * D_];
__device__ float g_pe  [(size_t)MPAT * D_];
__device__ float g_h   [(size_t)MTOK * D_];
__device__ float g_z   [(size_t)MTOK * D_];
__device__ float g_q   [(size_t)MTOK * D_];
__device__ float g_k   [(size_t)MTOK * D_];
__device__ float g_v   [(size_t)MTOK * D_];
__device__ float g_y   [(size_t)MTOK * D_];
__device__ float g_sc  [(size_t)BH_ * S_ * S_];
__device__ float g_mlp [(size_t)MTOK * FF_];
__device__ float g_cls [B_ * D_];
__device__ float g_clsln[B_ * D_];

// ---------------- SGEMM: C = A[MxK] @ B[KxN] + bias, epilogues ----------------
// EPI: 0 = bias, 1 = bias + residual (C = res + acc + bias), 2 = bias + exact GELU
#define BM 128
#define BN 128
#define BKK 8
#define TM 8
#define TN 8

template <int EPI>
__global__ __launch_bounds__(256)
void sgemm_k(const float* __restrict__ A, const float* __restrict__ B,
             const float* __restrict__ bias, const float* __restrict__ res,
             float* __restrict__ C, int M, int N, int K)
{
    __shared__ float As[BKK][BM];
    __shared__ float Bs[BKK][BN];

    const int tid   = threadIdx.x;
    const int mBase = blockIdx.y * BM;
    const int nBase = blockIdx.x * BN;

    // A tile: 128 rows x 8 cols -> 256 float4 loads
    const int aRow = tid >> 1;
    const int aCol = (tid & 1) * 4;
    // B tile: 8 rows x 128 cols -> 256 float4 loads
    const int bRow = tid >> 5;
    const int bCol = (tid & 31) * 4;

    const int tx = tid & 15;
    const int ty = tid >> 4;

    const int aRowG = min(mBase + aRow, M - 1);          // clamp (stores predicated)
    const int bColG = min(nBase + bCol, N - 4);          // N is a multiple of 4

    float acc[TM][TN];
#pragma unroll
    for (int i = 0; i < TM; i++)
#pragma unroll
        for (int j = 0; j < TN; j++) acc[i][j] = 0.f;

    for (int k0 = 0; k0 < K; k0 += BKK) {
        float4 a4 = *(const float4*)(A + (size_t)aRowG * K + k0 + aCol);
        float4 b4 = *(const float4*)(B + (size_t)(k0 + bRow) * N + bColG);
        As[aCol + 0][aRow] = a4.x;
        As[aCol + 1][aRow] = a4.y;
        As[aCol + 2][aRow] = a4.z;
        As[aCol + 3][aRow] = a4.w;
        *(float4*)(&Bs[bRow][bCol]) = b4;
        __syncthreads();

#pragma unroll
        for (int kk = 0; kk < BKK; kk++) {
            float a_reg[TM], b_reg[TN];
#pragma unroll
            for (int i = 0; i < TM; i++) a_reg[i] = As[kk][ty * TM + i];
#pragma unroll
            for (int j = 0; j < TN; j++) b_reg[j] = Bs[kk][tx * TN + j];
#pragma unroll
            for (int i = 0; i < TM; i++)
#pragma unroll
                for (int j = 0; j < TN; j++)
                    acc[i][j] += a_reg[i] * b_reg[j];
        }
        __syncthreads();
    }

#pragma unroll
    for (int i = 0; i < TM; i++) {
        int r = mBase + ty * TM + i;
        if (r >= M) continue;
#pragma unroll
        for (int j = 0; j < TN; j++) {
            int c = nBase + tx * TN + j;
            if (c >= N) continue;
            float v = acc[i][j] + bias[c];
            size_t idx = (size_t)r * N + c;
            if (EPI == 1) {
                C[idx] = res[idx] + v;
            } else if (EPI == 2) {
                C[idx] = 0.5f * v * (1.0f + erff(v * 0.70710678118654752f));
            } else {
                C[idx] = v;
            }
        }
    }
}

// ---------------- block reduce helper ----------------
__device__ float blockReduceSum(float v)
{
    __shared__ float red[8];
    __syncthreads();                       // protect red[] across back-to-back calls
    int lane = threadIdx.x & 31, w = threadIdx.x >> 5;
#pragma unroll
    for (int o = 16; o; o >>= 1) v += __shfl_xor_sync(0xffffffffu, v, o);
    if (lane == 0) red[w] = v;
    __syncthreads();
    if (w == 0) {
        float r = (lane < 8) ? red[lane] : 0.f;
#pragma unroll
        for (int o = 4; o; o >>= 1) r += __shfl_xor_sync(0xffffffffu, r, o);
        if (lane == 0) red[0] = r;
    }
    __syncthreads();
    return red[0];
}

// ---------------- LayerNorm: eps OUTSIDE sqrt ----------------
__global__ void ln_k(const float* __restrict__ x, const float* __restrict__ w,
                     const float* __restrict__ b, float* __restrict__ out)
{
    int row = blockIdx.x;
    const float* xr = x + (size_t)row * D_;
    __shared__ float sm[D_];
    float part = 0.f;
    for (int d = threadIdx.x; d < D_; d += blockDim.x) {
        float t = xr[d];
        sm[d] = t;
        part += t;
    }
    float mean = blockReduceSum(part) * (1.0f / D_);
    float p2 = 0.f;
    for (int d = threadIdx.x; d < D_; d += blockDim.x) {
        float t = sm[d] - mean;
        p2 += t * t;
    }
    float var = blockReduceSum(p2) * (1.0f / D_);
    float inv = 1.0f / (sqrtf(var) + 1e-5f);
    float* orow = out + (size_t)row * D_;
    for (int d = threadIdx.x; d < D_; d += blockDim.x)
        orow[d] = (sm[d] - mean) * inv * w[d] + b[d];
}

// ---------------- patch gather: x[B,3,224,224] -> A[B*196, 768] ----------------
__global__ void patch_k(const float* __restrict__ x, float* __restrict__ A)
{
    size_t idx = (size_t)blockIdx.x * 256 + threadIdx.x;
    if (idx >= (size_t)MPAT * D_) return;
    int kf = (int)(idx % D_);
    size_t r = idx / D_;
    int n = (int)(r % NP_);
    int b = (int)(r / NP_);
    int ph = n / 14, pw = n % 14;
    int c  = kf >> 8;
    int py = (kf >> 4) & 15;
    int px = kf & 15;
    A[idx] = x[(((size_t)b * 3 + c) * 224 + (ph * 16 + py)) * 224 + (pw * 16 + px)];
}

// ---------------- assemble: h = [cls | patch_embed] + pos_emb ----------------
__global__ void assemble_k(const float* __restrict__ pe, const float* __restrict__ cls,
                           const float* __restrict__ pos, float* __restrict__ h)
{
    size_t idx = (size_t)blockIdx.x * 256 + threadIdx.x;
    if (idx >= (size_t)MTOK * D_) return;
    int d = (int)(idx % D_);
    size_t r = idx / D_;
    int s = (int)(r % S_);
    int b = (int)(r / S_);
    float base = (s == 0) ? cls[d] : pe[((size_t)b * NP_ + (s - 1)) * D_ + d];
    h[idx] = base + pos[(size_t)s * D_ + d];
}

// ---------------- attention: scores = q @ k^T / 8 ----------------
__global__ void scores_k(const float* __restrict__ q, const float* __restrict__ kmat,
                         float* __restrict__ s)
{
    int bh = blockIdx.x;
    int b = bh / NH_, h = bh % NH_;
    int i0 = blockIdx.y * 16;

    __shared__ float qs[16][HD_];
    for (int idx = threadIdx.x; idx < 16 * HD_; idx += 256) {
        int ii = idx >> 6, d = idx & 63;
        int si = i0 + ii;
        qs[ii][d] = (si < S_) ? q[((size_t)(b * S_ + si)) * D_ + h * HD_ + d] : 0.f;
    }
    __syncthreads();

    for (int j = threadIdx.x; j < S_; j += 256) {
        const float* kr = kmat + ((size_t)(b * S_ + j)) * D_ + h * HD_;
        float acc[16];
#pragma unroll
        for (int ii = 0; ii < 16; ii++) acc[ii] = 0.f;
        for (int d = 0; d < HD_; d++) {
            float kv = kr[d];
#pragma unroll
            for (int ii = 0; ii < 16; ii++) acc[ii] += qs[ii][d] * kv;
        }
#pragma unroll
        for (int ii = 0; ii < 16; ii++) {
            int i = i0 + ii;
            if (i < S_) s[((size_t)bh * S_ + i) * S_ + j] = acc[ii] * 0.125f;
        }
    }
}

// ---------------- softmax: one warp per row of 197 ----------------
__global__ void softmax_k(float* __restrict__ s)
{
    int row = blockIdx.x * blockDim.y + threadIdx.y;
    if (row >= BH_ * S_) return;
    float* p = s + (size_t)row * S_;
    int lane = threadIdx.x;
    float buf[7];
    int cnt = 0;
    float m = -1e30f;
    for (int j = lane; j < S_; j += 32) {
        buf[cnt] = p[j];
        m = fmaxf(m, buf[cnt]);
        cnt++;
    }
#pragma unroll
    for (int o = 16; o; o >>= 1) m = fmaxf(m, __shfl_xor_sync(0xffffffffu, m, o));
    float sum = 0.f;
    cnt = 0;
    for (int j = lane; j < S_; j += 32) {
        float e = __expf(buf[cnt] - m);
        buf[cnt] = e;
        sum += e;
        cnt++;
    }
#pragma unroll
    for (int o = 16; o; o >>= 1) sum += __shfl_xor_sync(0xffffffffu, sum, o);
    float inv = 1.0f / sum;
    cnt = 0;
    for (int j = lane; j < S_; j += 32) p[j] = buf[cnt++] * inv;
}

// ---------------- y = attn @ v ----------------
__global__ void av_k(const float* __restrict__ s, const float* __restrict__ v,
                     float* __restrict__ y)
{
    int bh = blockIdx.x;
    int b = bh / NH_, h = bh % NH_;
    int i0 = blockIdx.y * 16;

    __shared__ float ps[16][S_];
    for (int idx = threadIdx.x; idx < 16 * S_; idx += 256) {
        int ii = idx / S_, j = idx % S_;
        int si = i0 + ii;
        ps[ii][j] = (si < S_) ? s[((size_t)bh * S_ + si) * S_ + j] : 0.f;
    }
    __syncthreads();

    int d = threadIdx.x & 63;
    int ig = threadIdx.x >> 6;        // 0..3
    float acc[4] = {0.f, 0.f, 0.f, 0.f};
    for (int j = 0; j < S_; j++) {
        float vv = v[((size_t)(b * S_ + j)) * D_ + h * HD_ + d];
#pragma unroll
        for (int t = 0; t < 4; t++) acc[t] += ps[ig + t * 4][j] * vv;
    }
#pragma unroll
    for (int t = 0; t < 4; t++) {
        int i = i0 + ig + t * 4;
        if (i < S_) y[((size_t)(b * S_ + i)) * D_ + h * HD_ + d] = acc[t];
    }
}

// ---------------- cls gather ----------------
__global__ void clsgather_k(const float* __restrict__ h, float* __restrict__ o)
{
    int idx = blockIdx.x * 256 + threadIdx.x;
    if (idx >= B_ * D_) return;
    int b = idx / D_, d = idx % D_;
    o[idx] = h[((size_t)b * S_) * D_ + d];
}

// ---------------- host side ----------------
static float* symaddr(const void* sym_)
{
    void* p = nullptr;
    cudaGetSymbolAddress(&p, sym_);
    return (float*)p;
}

static void gemm(const float* A, const float* Bm, const float* bias, const float* res,
                 float* C, int M, int N, int K, int epi)
{
    dim3 grid((N + BN - 1) / BN, (M + BM - 1) / BM);
    if (epi == 0)      sgemm_k<0><<<grid, 256>>>(A, Bm, bias, nullptr, C, M, N, K);
    else if (epi == 1) sgemm_k<1><<<grid, 256>>>(A, Bm, bias, res, C, M, N, K);
    else               sgemm_k<2><<<grid, 256>>>(A, Bm, bias, nullptr, C, M, N, K);
}

extern "C" void kernel_launch(void* const* d_in, const int* in_sizes, int n_in,
                              void* d_out, int out_size)
{
    const float* x         = (const float*)d_in[0];
    const float* patch_w   = (const float*)d_in[1];
    const float* patch_b   = (const float*)d_in[2];
    const float* cls_token = (const float*)d_in[3];
    const float* pos_emb   = (const float*)d_in[4];
    const float* ln1_w     = (const float*)d_in[5];
    const float* ln1_b     = (const float*)d_in[6];
    const float* wq        = (const float*)d_in[7];
    const float* bq        = (const float*)d_in[8];
    const float* wk        = (const float*)d_in[9];
    const float* bk        = (const float*)d_in[10];
    const float* wv        = (const float*)d_in[11];
    const float* bv        = (const float*)d_in[12];
    const float* wy        = (const float*)d_in[13];
    const float* by        = (const float*)d_in[14];
    const float* ln2_w     = (const float*)d_in[15];
    const float* ln2_b     = (const float*)d_in[16];
    const float* mlp_w1    = (const float*)d_in[17];
    const float* mlp_b1    = (const float*)d_in[18];
    const float* mlp_w2    = (const float*)d_in[19];
    const float* mlp_b2    = (const float*)d_in[20];
    const float* head_ln_w = (const float*)d_in[21];
    const float* head_ln_b = (const float*)d_in[22];
    const float* head_w    = (const float*)d_in[23];
    const float* head_b    = (const float*)d_in[24];

    float* A     = symaddr(g_A);
    float* pe    = symaddr(g_pe);
    float* h     = symaddr(g_h);
    float* z     = symaddr(g_z);
    float* q     = symaddr(g_q);
    float* k     = symaddr(g_k);
    float* v     = symaddr(g_v);
    float* y     = symaddr(g_y);
    float* sc    = symaddr(g_sc);
    float* mlp   = symaddr(g_mlp);
    float* cls   = symaddr(g_cls);
    float* clsln = symaddr(g_clsln);

    // patch embed
    patch_k<<<(int)(((size_t)MPAT * D_ + 255) / 256), 256>>>(x, A);
    gemm(A, patch_w, patch_b, nullptr, pe, MPAT, D_, D_, 0);
    assemble_k<<<(int)(((size_t)MTOK * D_ + 255) / 256), 256>>>(pe, cls_token, pos_emb, h);

    const int sm_rows = BH_ * S_;
    for (int l = 0; l < L_; l++) {
        const float* l1w = ln1_w + (size_t)l * D_;
        const float* l1b = ln1_b + (size_t)l * D_;
        const float* l2w = ln2_w + (size_t)l * D_;
        const float* l2b = ln2_b + (size_t)l * D_;
        const float* wq_l = wq + (size_t)l * D_ * D_;
        const float* wk_l = wk + (size_t)l * D_ * D_;
        const float* wv_l = wv + (size_t)l * D_ * D_;
        const float* wy_l = wy + (size_t)l * D_ * D_;
        const float* w1_l = mlp_w1 + (size_t)l * D_ * FF_;
        const float* w2_l = mlp_w2 + (size_t)l * FF_ * D_;

        ln_k<<<MTOK, 256>>>(h, l1w, l1b, z);
        gemm(z, wq_l, bq + (size_t)l * D_, nullptr, q, MTOK, D_, D_, 0);
        gemm(z, wk_l, bk + (size_t)l * D_, nullptr, k, MTOK, D_, D_, 0);
        gemm(z, wv_l, bv + (size_t)l * D_, nullptr, v, MTOK, D_, D_, 0);

        scores_k<<<dim3(BH_, (S_ + 15) / 16), 256>>>(q, k, sc);
        softmax_k<<<(sm_rows + 7) / 8, dim3(32, 8)>>>(sc);
        av_k<<<dim3(BH_, (S_ + 15) / 16), 256>>>(sc, v, y);

        gemm(y, wy_l, by + (size_t)l * D_, h, h, MTOK, D_, D_, 1);   // residual 1

        ln_k<<<MTOK, 256>>>(h, l2w, l2b, z);
        gemm(z, w1_l, mlp_b1 + (size_t)l * FF_, nullptr, mlp, MTOK, FF_, D_, 2);   // GELU
        gemm(mlp, w2_l, mlp_b2 + (size_t)l * D_, h, h, MTOK, D_, FF_, 1);          // residual 2
    }

    // head
    clsgather_k<<<(B_ * D_ + 255) / 256, 256>>>(h, cls);
    ln_k<<<B_, 256>>>(cls, head_ln_w, head_ln_b, clsln);
    gemm(clsln, head_w, head_b, nullptr, (float*)d_out, B_, NC_, D_, 0);
}

// round 4
// speedup vs baseline: 1.5124x; 1.5124x over previous
#include <cuda_runtime.h>
#include <math.h>
#include <stddef.h>

// ---------------- problem constants ----------------
#define B_   32
#define S_   197
#define D_   768
#define L_   12
#define FF_  3072
#define NH_  12
#define HD_  64
#define NC_  1000
#define NP_  196          // patches per image
#define MTOK (B_ * S_)    // 6304 tokens
#define MPAT (B_ * NP_)   // 6272 patch rows
#define BH_  (B_ * NH_)   // 384 attention matrices

// ---------------- scratch (static device globals; no allocs allowed) ----------------
__device__ float g_A   [(size_t)MPAT * D_];
__device__ float g_pe  [(size_t)MPAT * D_];
__device__ float g_h   [(size_t)MTOK * D_];
__device__ float g_z   [(size_t)MTOK * D_];
__device__ float g_q   [(size_t)MTOK * D_];
__device__ float g_k   [(size_t)MTOK * D_];
__device__ float g_v   [(size_t)MTOK * D_];
__device__ float g_y   [(size_t)MTOK * D_];
__device__ float g_sc  [(size_t)BH_ * S_ * S_];
__device__ float g_mlp [(size_t)MTOK * FF_];
__device__ float g_cls [B_ * D_];
__device__ float g_clsln[B_ * D_];

// ======================================================================
// TF32 tensor-core GEMM with fp32-accuracy emulation (3xTF32 split).
// C = A[MxK] @ B[KxN] (+bias, epilogues). Requires K%16==0, N%128==0.
// EPI: 0 = bias, 1 = bias+residual, 2 = bias+exact GELU
// ======================================================================
#define GBM 128
#define GBN 128
#define GBK 16
#define ASTR 20     // padded A smem stride (conflict-free fragment loads)
#define BSTR 136    // padded B smem stride

__device__ __forceinline__ unsigned f2tf32(float f) {
    unsigned u;
    asm volatile("cvt.rna.tf32.f32 %0, %1;" : "=r"(u) : "f"(f));
    return u;
}

__device__ __forceinline__ void split_tf32(float f, unsigned& hi, unsigned& lo) {
    hi = f2tf32(f);
    float r = f - __uint_as_float(hi);
    lo = f2tf32(r);
}

__device__ __forceinline__ void mma_tf32(float* c, const unsigned* a, const unsigned* b) {
    asm volatile(
        "mma.sync.aligned.m16n8k8.row.col.f32.tf32.tf32.f32 "
        "{%0,%1,%2,%3}, {%4,%5,%6,%7}, {%8,%9}, {%0,%1,%2,%3};\n"
        : "+f"(c[0]), "+f"(c[1]), "+f"(c[2]), "+f"(c[3])
        : "r"(a[0]), "r"(a[1]), "r"(a[2]), "r"(a[3]), "r"(b[0]), "r"(b[1]));
}

__device__ __forceinline__ void cp16(float* smem_dst, const float* gsrc) {
    unsigned d = (unsigned)__cvta_generic_to_shared(smem_dst);
    asm volatile("cp.async.cg.shared.global [%0], [%1], 16;" :: "r"(d), "l"(gsrc));
}

template <int EPI>
__device__ void gemm_tf32_body(const float* __restrict__ A, const float* __restrict__ Bm,
                               const float* __restrict__ bias, const float* __restrict__ res,
                               float* __restrict__ C, int M, int N, int K,
                               int mBase, int nBase)
{
    __shared__ float As[2][GBM * ASTR];
    __shared__ float Bs[2][GBK * BSTR];

    const int tid  = threadIdx.x;
    const int warp = tid >> 5;
    const int lane = tid & 31;
    const int grp  = lane >> 2;   // 0..7
    const int qid  = lane & 3;    // 0..3
    const int wM   = warp >> 2;   // 0..1
    const int wN   = warp & 3;    // 0..3

    // gmem staging indices
    const int arow = tid >> 1;              // 0..127
    const int acol = (tid & 1) * 8;         // 0 or 8
    const int arG  = min(mBase + arow, M - 1);
    const int brow = tid >> 4;              // 0..15
    const int bcol = (tid & 15) * 8;

    float acc[4][4][4];
#pragma unroll
    for (int mi = 0; mi < 4; mi++)
#pragma unroll
        for (int ni = 0; ni < 4; ni++)
#pragma unroll
            for (int r = 0; r < 4; r++) acc[mi][ni][r] = 0.f;

    const int NK = K / GBK;

    // prologue: stage 0
    {
        const float* ag = A + (size_t)arG * K + acol;
        float* as = &As[0][arow * ASTR + acol];
        cp16(as, ag); cp16(as + 4, ag + 4);
        const float* bg = Bm + (size_t)brow * N + nBase + bcol;
        float* bs = &Bs[0][brow * BSTR + bcol];
        cp16(bs, bg); cp16(bs + 4, bg + 4);
        asm volatile("cp.async.commit_group;");
    }

    for (int kt = 0; kt < NK; kt++) {
        if (kt + 1 < NK) {
            int k0 = (kt + 1) * GBK;
            int s  = (kt + 1) & 1;
            const float* ag = A + (size_t)arG * K + k0 + acol;
            float* as = &As[s][arow * ASTR + acol];
            cp16(as, ag); cp16(as + 4, ag + 4);
            const float* bg = Bm + (size_t)(k0 + brow) * N + nBase + bcol;
            float* bs = &Bs[s][brow * BSTR + bcol];
            cp16(bs, bg); cp16(bs + 4, bg + 4);
            asm volatile("cp.async.commit_group;");
            asm volatile("cp.async.wait_group 1;");
        } else {
            asm volatile("cp.async.wait_group 0;");
        }
        __syncthreads();

        const float* As_ = As[kt & 1];
        const float* Bs_ = Bs[kt & 1];

#pragma unroll
        for (int ks = 0; ks < GBK; ks += 8) {
            unsigned ahi[4][4], alo[4][4];
#pragma unroll
            for (int mi = 0; mi < 4; mi++) {
                int r = wM * 64 + mi * 16 + grp;
                float f0 = As_[r * ASTR + ks + qid];
                float f1 = As_[(r + 8) * ASTR + ks + qid];
                float f2 = As_[r * ASTR + ks + qid + 4];
                float f3 = As_[(r + 8) * ASTR + ks + qid + 4];
                split_tf32(f0, ahi[mi][0], alo[mi][0]);
                split_tf32(f1, ahi[mi][1], alo[mi][1]);
                split_tf32(f2, ahi[mi][2], alo[mi][2]);
                split_tf32(f3, ahi[mi][3], alo[mi][3]);
            }
            unsigned bhi[4][2], blo[4][2];
#pragma unroll
            for (int ni = 0; ni < 4; ni++) {
                int n = wN * 32 + ni * 8 + grp;
                float g0 = Bs_[(ks + qid) * BSTR + n];
                float g1 = Bs_[(ks + qid + 4) * BSTR + n];
                split_tf32(g0, bhi[ni][0], blo[ni][0]);
                split_tf32(g1, bhi[ni][1], blo[ni][1]);
            }
#pragma unroll
            for (int mi = 0; mi < 4; mi++)
#pragma unroll
                for (int ni = 0; ni < 4; ni++) {
                    mma_tf32(acc[mi][ni], ahi[mi], bhi[ni]);
                    mma_tf32(acc[mi][ni], ahi[mi], blo[ni]);
                    mma_tf32(acc[mi][ni], alo[mi], bhi[ni]);
                }
        }
        __syncthreads();
    }

    // epilogue
#pragma unroll
    for (int mi = 0; mi < 4; mi++) {
        int r0 = mBase + wM * 64 + mi * 16 + grp;
#pragma unroll
        for (int ni = 0; ni < 4; ni++) {
            int c0 = nBase + wN * 32 + ni * 8 + qid * 2;
            float b0 = bias[c0], b1 = bias[c0 + 1];
#pragma unroll
            for (int half = 0; half < 2; half++) {
                int r = r0 + half * 8;
                if (r >= M) continue;
                float v0 = acc[mi][ni][half * 2 + 0] + b0;
                float v1 = acc[mi][ni][half * 2 + 1] + b1;
                size_t i0 = (size_t)r * N + c0;
                if (EPI == 1) {
                    C[i0]     = res[i0]     + v0;
                    C[i0 + 1] = res[i0 + 1] + v1;
                } else if (EPI == 2) {
                    C[i0]     = 0.5f * v0 * (1.0f + erff(v0 * 0.70710678118654752f));
                    C[i0 + 1] = 0.5f * v1 * (1.0f + erff(v1 * 0.70710678118654752f));
                } else {
                    C[i0]     = v0;
                    C[i0 + 1] = v1;
                }
            }
        }
    }
}

template <int EPI>
__global__ __launch_bounds__(256)
void gemm_tf32_k(const float* __restrict__ A, const float* __restrict__ B,
                 const float* __restrict__ bias, const float* __restrict__ res,
                 float* __restrict__ C, int M, int N, int K)
{
    gemm_tf32_body<EPI>(A, B, bias, res, C, M, N, K,
                        blockIdx.y * GBM, blockIdx.x * GBN);
}

// fused QKV: blockIdx.z picks (weight, bias, output)
__global__ __launch_bounds__(256)
void qkv_tf32_k(const float* __restrict__ Z,
                const float* __restrict__ wq, const float* __restrict__ wk,
                const float* __restrict__ wv,
                const float* __restrict__ bq, const float* __restrict__ bk,
                const float* __restrict__ bv,
                float* __restrict__ q, float* __restrict__ k, float* __restrict__ v)
{
    const float* W; const float* bb; float* out;
    if (blockIdx.z == 0)      { W = wq; bb = bq; out = q; }
    else if (blockIdx.z == 1) { W = wk; bb = bk; out = k; }
    else                      { W = wv; bb = bv; out = v; }
    gemm_tf32_body<0>(Z, W, bb, nullptr, out, MTOK, D_, D_,
                      blockIdx.y * GBM, blockIdx.x * GBN);
}

// ---------------- small SIMT GEMM (head only: N=1000) ----------------
#define BM 128
#define BN 128
#define BKK 8
#define TM 8
#define TN 8

__global__ __launch_bounds__(256)
void sgemm_head_k(const float* __restrict__ A, const float* __restrict__ B,
                  const float* __restrict__ bias, float* __restrict__ C,
                  int M, int N, int K)
{
    __shared__ float As[BKK][BM];
    __shared__ float Bs[BKK][BN];

    const int tid   = threadIdx.x;
    const int mBase = blockIdx.y * BM;
    const int nBase = blockIdx.x * BN;

    const int aRow = tid >> 1;
    const int aCol = (tid & 1) * 4;
    const int bRow = tid >> 5;
    const int bCol = (tid & 31) * 4;

    const int tx = tid & 15;
    const int ty = tid >> 4;

    const int aRowG = min(mBase + aRow, M - 1);
    const int bColG = min(nBase + bCol, N - 4);

    float acc[TM][TN];
#pragma unroll
    for (int i = 0; i < TM; i++)
#pragma unroll
        for (int j = 0; j < TN; j++) acc[i][j] = 0.f;

    for (int k0 = 0; k0 < K; k0 += BKK) {
        float4 a4 = *(const float4*)(A + (size_t)aRowG * K + k0 + aCol);
        float4 b4 = *(const float4*)(B + (size_t)(k0 + bRow) * N + bColG);
        As[aCol + 0][aRow] = a4.x;
        As[aCol + 1][aRow] = a4.y;
        As[aCol + 2][aRow] = a4.z;
        As[aCol + 3][aRow] = a4.w;
        *(float4*)(&Bs[bRow][bCol]) = b4;
        __syncthreads();

#pragma unroll
        for (int kk = 0; kk < BKK; kk++) {
            float a_reg[TM], b_reg[TN];
#pragma unroll
            for (int i = 0; i < TM; i++) a_reg[i] = As[kk][ty * TM + i];
#pragma unroll
            for (int j = 0; j < TN; j++) b_reg[j] = Bs[kk][tx * TN + j];
#pragma unroll
            for (int i = 0; i < TM; i++)
#pragma unroll
                for (int j = 0; j < TN; j++)
                    acc[i][j] += a_reg[i] * b_reg[j];
        }
        __syncthreads();
    }

#pragma unroll
    for (int i = 0; i < TM; i++) {
        int r = mBase + ty * TM + i;
        if (r >= M) continue;
#pragma unroll
        for (int j = 0; j < TN; j++) {
            int c = nBase + tx * TN + j;
            if (c >= N) continue;
            C[(size_t)r * N + c] = acc[i][j] + bias[c];
        }
    }
}

// ---------------- block reduce helper ----------------
__device__ float blockReduceSum(float v)
{
    __shared__ float red[8];
    __syncthreads();
    int lane = threadIdx.x & 31, w = threadIdx.x >> 5;
#pragma unroll
    for (int o = 16; o; o >>= 1) v += __shfl_xor_sync(0xffffffffu, v, o);
    if (lane == 0) red[w] = v;
    __syncthreads();
    if (w == 0) {
        float r = (lane < 8) ? red[lane] : 0.f;
#pragma unroll
        for (int o = 4; o; o >>= 1) r += __shfl_xor_sync(0xffffffffu, r, o);
        if (lane == 0) red[0] = r;
    }
    __syncthreads();
    return red[0];
}

// ---------------- LayerNorm: eps OUTSIDE sqrt ----------------
__global__ void ln_k(const float* __restrict__ x, const float* __restrict__ w,
                     const float* __restrict__ b, float* __restrict__ out)
{
    int row = blockIdx.x;
    const float* xr = x + (size_t)row * D_;
    __shared__ float sm[D_];
    float part = 0.f;
    for (int d = threadIdx.x; d < D_; d += blockDim.x) {
        float t = xr[d];
        sm[d] = t;
        part += t;
    }
    float mean = blockReduceSum(part) * (1.0f / D_);
    float p2 = 0.f;
    for (int d = threadIdx.x; d < D_; d += blockDim.x) {
        float t = sm[d] - mean;
        p2 += t * t;
    }
    float var = blockReduceSum(p2) * (1.0f / D_);
    float inv = 1.0f / (sqrtf(var) + 1e-5f);
    float* orow = out + (size_t)row * D_;
    for (int d = threadIdx.x; d < D_; d += blockDim.x)
        orow[d] = (sm[d] - mean) * inv * w[d] + b[d];
}

// ---------------- patch gather: x[B,3,224,224] -> A[B*196, 768] ----------------
__global__ void patch_k(const float* __restrict__ x, float* __restrict__ A)
{
    size_t idx = (size_t)blockIdx.x * 256 + threadIdx.x;
    if (idx >= (size_t)MPAT * D_) return;
    int kf = (int)(idx % D_);
    size_t r = idx / D_;
    int n = (int)(r % NP_);
    int b = (int)(r / NP_);
    int ph = n / 14, pw = n % 14;
    int c  = kf >> 8;
    int py = (kf >> 4) & 15;
    int px = kf & 15;
    A[idx] = x[(((size_t)b * 3 + c) * 224 + (ph * 16 + py)) * 224 + (pw * 16 + px)];
}

// ---------------- assemble: h = [cls | patch_embed] + pos_emb ----------------
__global__ void assemble_k(const float* __restrict__ pe, const float* __restrict__ cls,
                           const float* __restrict__ pos, float* __restrict__ h)
{
    size_t idx = (size_t)blockIdx.x * 256 + threadIdx.x;
    if (idx >= (size_t)MTOK * D_) return;
    int d = (int)(idx % D_);
    size_t r = idx / D_;
    int s = (int)(r % S_);
    int b = (int)(r / S_);
    float base = (s == 0) ? cls[d] : pe[((size_t)b * NP_ + (s - 1)) * D_ + d];
    h[idx] = base + pos[(size_t)s * D_ + d];
}

// ---------------- attention: scores = q @ k^T / 8 ----------------
__global__ void scores_k(const float* __restrict__ q, const float* __restrict__ kmat,
                         float* __restrict__ s)
{
    int bh = blockIdx.x;
    int b = bh / NH_, h = bh % NH_;
    int i0 = blockIdx.y * 16;

    __shared__ float qs[16][HD_];
    for (int idx = threadIdx.x; idx < 16 * HD_; idx += 256) {
        int ii = idx >> 6, d = idx & 63;
        int si = i0 + ii;
        qs[ii][d] = (si < S_) ? q[((size_t)(b * S_ + si)) * D_ + h * HD_ + d] : 0.f;
    }
    __syncthreads();

    for (int j = threadIdx.x; j < S_; j += 256) {
        const float* kr = kmat + ((size_t)(b * S_ + j)) * D_ + h * HD_;
        float acc[16];
#pragma unroll
        for (int ii = 0; ii < 16; ii++) acc[ii] = 0.f;
        for (int d = 0; d < HD_; d++) {
            float kv = kr[d];
#pragma unroll
            for (int ii = 0; ii < 16; ii++) acc[ii] += qs[ii][d] * kv;
        }
#pragma unroll
        for (int ii = 0; ii < 16; ii++) {
            int i = i0 + ii;
            if (i < S_) s[((size_t)bh * S_ + i) * S_ + j] = acc[ii] * 0.125f;
        }
    }
}

// ---------------- softmax: one warp per row of 197 ----------------
__global__ void softmax_k(float* __restrict__ s)
{
    int row = blockIdx.x * blockDim.y + threadIdx.y;
    if (row >= BH_ * S_) return;
    float* p = s + (size_t)row * S_;
    int lane = threadIdx.x;
    float buf[7];
    int cnt = 0;
    float m = -1e30f;
    for (int j = lane; j < S_; j += 32) {
        buf[cnt] = p[j];
        m = fmaxf(m, buf[cnt]);
        cnt++;
    }
#pragma unroll
    for (int o = 16; o; o >>= 1) m = fmaxf(m, __shfl_xor_sync(0xffffffffu, m, o));
    float sum = 0.f;
    cnt = 0;
    for (int j = lane; j < S_; j += 32) {
        float e = __expf(buf[cnt] - m);
        buf[cnt] = e;
        sum += e;
        cnt++;
    }
#pragma unroll
    for (int o = 16; o; o >>= 1) sum += __shfl_xor_sync(0xffffffffu, sum, o);
    float inv = 1.0f / sum;
    cnt = 0;
    for (int j = lane; j < S_; j += 32) p[j] = buf[cnt++] * inv;
}

// ---------------- y = attn @ v ----------------
__global__ void av_k(const float* __restrict__ s, const float* __restrict__ v,
                     float* __restrict__ y)
{
    int bh = blockIdx.x;
    int b = bh / NH_, h = bh % NH_;
    int i0 = blockIdx.y * 16;

    __shared__ float ps[16][S_];
    for (int idx = threadIdx.x; idx < 16 * S_; idx += 256) {
        int ii = idx / S_, j = idx % S_;
        int si = i0 + ii;
        ps[ii][j] = (si < S_) ? s[((size_t)bh * S_ + si) * S_ + j] : 0.f;
    }
    __syncthreads();

    int d = threadIdx.x & 63;
    int ig = threadIdx.x >> 6;        // 0..3
    float acc[4] = {0.f, 0.f, 0.f, 0.f};
    for (int j = 0; j < S_; j++) {
        float vv = v[((size_t)(b * S_ + j)) * D_ + h * HD_ + d];
#pragma unroll
        for (int t = 0; t < 4; t++) acc[t] += ps[ig + t * 4][j] * vv;
    }
#pragma unroll
    for (int t = 0; t < 4; t++) {
        int i = i0 + ig + t * 4;
        if (i < S_) y[((size_t)(b * S_ + i)) * D_ + h * HD_ + d] = acc[t];
    }
}

// ---------------- cls gather ----------------
__global__ void clsgather_k(const float* __restrict__ h, float* __restrict__ o)
{
    int idx = blockIdx.x * 256 + threadIdx.x;
    if (idx >= B_ * D_) return;
    int b = idx / D_, d = idx % D_;
    o[idx] = h[((size_t)b * S_) * D_ + d];
}

// ---------------- host side ----------------
static float* symaddr(const void* sym_)
{
    void* p = nullptr;
    cudaGetSymbolAddress(&p, sym_);
    return (float*)p;
}

static void gemm_tc(const float* A, const float* Bm, const float* bias, const float* res,
                    float* C, int M, int N, int K, int epi)
{
    dim3 grid(N / GBN, (M + GBM - 1) / GBM);
    if (epi == 0)      gemm_tf32_k<0><<<grid, 256>>>(A, Bm, bias, nullptr, C, M, N, K);
    else if (epi == 1) gemm_tf32_k<1><<<grid, 256>>>(A, Bm, bias, res, C, M, N, K);
    else               gemm_tf32_k<2><<<grid, 256>>>(A, Bm, bias, nullptr, C, M, N, K);
}

extern "C" void kernel_launch(void* const* d_in, const int* in_sizes, int n_in,
                              void* d_out, int out_size)
{
    const float* x         = (const float*)d_in[0];
    const float* patch_w   = (const float*)d_in[1];
    const float* patch_b   = (const float*)d_in[2];
    const float* cls_token = (const float*)d_in[3];
    const float* pos_emb   = (const float*)d_in[4];
    const float* ln1_w     = (const float*)d_in[5];
    const float* ln1_b     = (const float*)d_in[6];
    const float* wq        = (const float*)d_in[7];
    const float* bq        = (const float*)d_in[8];
    const float* wk        = (const float*)d_in[9];
    const float* bk        = (const float*)d_in[10];
    const float* wv        = (const float*)d_in[11];
    const float* bv        = (const float*)d_in[12];
    const float* wy        = (const float*)d_in[13];
    const float* by        = (const float*)d_in[14];
    const float* ln2_w     = (const float*)d_in[15];
    const float* ln2_b     = (const float*)d_in[16];
    const float* mlp_w1    = (const float*)d_in[17];
    const float* mlp_b1    = (const float*)d_in[18];
    const float* mlp_w2    = (const float*)d_in[19];
    const float* mlp_b2    = (const float*)d_in[20];
    const float* head_ln_w = (const float*)d_in[21];
    const float* head_ln_b = (const float*)d_in[22];
    const float* head_w    = (const float*)d_in[23];
    const float* head_b    = (const float*)d_in[24];

    float* A     = symaddr(g_A);
    float* pe    = symaddr(g_pe);
    float* h     = symaddr(g_h);
    float* z     = symaddr(g_z);
    float* q     = symaddr(g_q);
    float* k     = symaddr(g_k);
    float* v     = symaddr(g_v);
    float* y     = symaddr(g_y);
    float* sc    = symaddr(g_sc);
    float* mlp   = symaddr(g_mlp);
    float* cls   = symaddr(g_cls);
    float* clsln = symaddr(g_clsln);

    // patch embed
    patch_k<<<(int)(((size_t)MPAT * D_ + 255) / 256), 256>>>(x, A);
    gemm_tc(A, patch_w, patch_b, nullptr, pe, MPAT, D_, D_, 0);
    assemble_k<<<(int)(((size_t)MTOK * D_ + 255) / 256), 256>>>(pe, cls_token, pos_emb, h);

    const int sm_rows = BH_ * S_;
    for (int l = 0; l < L_; l++) {
        const float* l1w = ln1_w + (size_t)l * D_;
        const float* l1b = ln1_b + (size_t)l * D_;
        const float* l2w = ln2_w + (size_t)l * D_;
        const float* l2b = ln2_b + (size_t)l * D_;
        const float* wq_l = wq + (size_t)l * D_ * D_;
        const float* wk_l = wk + (size_t)l * D_ * D_;
        const float* wv_l = wv + (size_t)l * D_ * D_;
        const float* wy_l = wy + (size_t)l * D_ * D_;
        const float* w1_l = mlp_w1 + (size_t)l * D_ * FF_;
        const float* w2_l = mlp_w2 + (size_t)l * FF_ * D_;

        ln_k<<<MTOK, 256>>>(h, l1w, l1b, z);

        // fused QKV (one launch, blockIdx.z selects q/k/v)
        qkv_tf32_k<<<dim3(D_ / GBN, (MTOK + GBM - 1) / GBM, 3), 256>>>(
            z, wq_l, wk_l, wv_l,
            bq + (size_t)l * D_, bk + (size_t)l * D_, bv + (size_t)l * D_,
            q, k, v);

        scores_k<<<dim3(BH_, (S_ + 15) / 16), 256>>>(q, k, sc);
        softmax_k<<<(sm_rows + 7) / 8, dim3(32, 8)>>>(sc);
        av_k<<<dim3(BH_, (S_ + 15) / 16), 256>>>(sc, v, y);

        gemm_tc(y, wy_l, by + (size_t)l * D_, h, h, MTOK, D_, D_, 1);   // residual 1

        ln_k<<<MTOK, 256>>>(h, l2w, l2b, z);
        gemm_tc(z, w1_l, mlp_b1 + (size_t)l * FF_, nullptr, mlp, MTOK, FF_, D_, 2);   // GELU
        gemm_tc(mlp, w2_l, mlp_b2 + (size_t)l * D_, h, h, MTOK, D_, FF_, 1);          // residual 2
    }

    // head
    clsgather_k<<<(B_ * D_ + 255) / 256, 256>>>(h, cls);
    ln_k<<<B_, 256>>>(cls, head_ln_w, head_ln_b, clsln);
    sgemm_head_k<<<dim3((NC_ + BN - 1) / BN, (B_ + BM - 1) / BM), 256>>>(
        clsln, head_w, head_b, (float*)d_out, B_, NC_, D_);
}

// round 7
// speedup vs baseline: 2.4253x; 1.6036x over previous
#include <cuda_runtime.h>
#include <cuda_bf16.h>
#include <math.h>
#include <stddef.h>
#include <stdint.h>

// ---------------- problem constants ----------------
#define B_   32
#define S_   197
#define D_   768
#define L_   12
#define FF_  3072
#define NH_  12
#define HD_  64
#define NC_  1000
#define NP_  196
#define MTOK (B_ * S_)    // 6304
#define MPAT (B_ * NP_)   // 6272
#define BH_  (B_ * NH_)   // 384

// ---------------- fp32 scratch ----------------
__device__ float g_pe  [(size_t)MPAT * D_];
__device__ float g_h   [(size_t)MTOK * D_];
__device__ float g_q   [(size_t)MTOK * D_];
__device__ float g_k   [(size_t)MTOK * D_];
__device__ float g_v   [(size_t)MTOK * D_];
__device__ float g_sc  [(size_t)BH_ * S_ * S_];
__device__ float g_cls [B_ * D_];
__device__ float g_clsln[B_ * D_];

// ---------------- bf16 hi/lo scratch ----------------
__device__ __nv_bfloat16 g_wq_h[(size_t)L_*D_*D_],  g_wq_l[(size_t)L_*D_*D_];
__device__ __nv_bfloat16 g_wk_h[(size_t)L_*D_*D_],  g_wk_l[(size_t)L_*D_*D_];
__device__ __nv_bfloat16 g_wv_h[(size_t)L_*D_*D_],  g_wv_l[(size_t)L_*D_*D_];
__device__ __nv_bfloat16 g_wy_h[(size_t)L_*D_*D_],  g_wy_l[(size_t)L_*D_*D_];
__device__ __nv_bfloat16 g_w1_h[(size_t)L_*D_*FF_], g_w1_l[(size_t)L_*D_*FF_];
__device__ __nv_bfloat16 g_w2_h[(size_t)L_*FF_*D_], g_w2_l[(size_t)L_*FF_*D_];
__device__ __nv_bfloat16 g_wp_h[(size_t)D_*D_],     g_wp_l[(size_t)D_*D_];
__device__ __nv_bfloat16 g_zh[(size_t)MTOK*D_],   g_zl[(size_t)MTOK*D_];
__device__ __nv_bfloat16 g_yh[(size_t)MTOK*D_],   g_yl[(size_t)MTOK*D_];
__device__ __nv_bfloat16 g_Ah[(size_t)MPAT*D_],   g_Al[(size_t)MPAT*D_];
__device__ __nv_bfloat16 g_m1h[(size_t)MTOK*FF_], g_m1l[(size_t)MTOK*FF_];

// ---------------- PTX helpers ----------------
__device__ __forceinline__ uint32_t smem_u32(const void* p) {
    uint32_t a;
    asm("{ .reg .u64 t; cvta.to.shared.u64 t, %1; cvt.u32.u64 %0, t; }" : "=r"(a) : "l"(p));
    return a;
}
__device__ __forceinline__ void cpa16(uint32_t saddr, const void* g) {
    asm volatile("cp.async.cg.shared.global [%0], [%1], 16;" :: "r"(saddr), "l"(g));
}
__device__ __forceinline__ void ldsm_x4(uint32_t* r, uint32_t a) {
    asm volatile("ldmatrix.sync.aligned.m8n8.x4.shared.b16 {%0,%1,%2,%3}, [%4];"
                 : "=r"(r[0]), "=r"(r[1]), "=r"(r[2]), "=r"(r[3]) : "r"(a));
}
__device__ __forceinline__ void ldsm_x2(uint32_t* r, uint32_t a) {
    asm volatile("ldmatrix.sync.aligned.m8n8.x2.shared.b16 {%0,%1}, [%2];"
                 : "=r"(r[0]), "=r"(r[1]) : "r"(a));
}
__device__ __forceinline__ void mma_bf16(float* c, const uint32_t* a, const uint32_t* b) {
    asm volatile(
        "mma.sync.aligned.m16n8k16.row.col.f32.bf16.bf16.f32 "
        "{%0,%1,%2,%3}, {%4,%5,%6,%7}, {%8,%9}, {%0,%1,%2,%3};"
        : "+f"(c[0]), "+f"(c[1]), "+f"(c[2]), "+f"(c[3])
        : "r"(a[0]), "r"(a[1]), "r"(a[2]), "r"(a[3]), "r"(b[0]), "r"(b[1]));
}
__device__ __forceinline__ void bsplit(float f, __nv_bfloat16& h, __nv_bfloat16& l) {
    h = __float2bfloat16_rn(f);
    l = __float2bfloat16_rn(f - __bfloat162float(h));
}

// ======================================================================
// bf16x3 mma.sync GEMM: C = (Ah+Al)[MxK] @ (Bh+Bl)[NxK]^T + bias
// EPI: 0 bias->f32, 1 bias+res->f32, 3 bias+GELU->bf16 hi/lo
// Tile 128x128x32, 8 warps (2x4), warp tile 64x32, double-buffered cp.async.
// Smem rows padded: 32 bf16 data + 8 pad = 40 elems = 80 bytes/row.
// ======================================================================
#define TCM 128
#define TCN 128
#define TCK 32
#define ROWB 80                   // padded row bytes
#define PARTB (128 * ROWB)        // 10240
#define BUFB  (4 * PARTB)         // Ah, Al, Bh, Bl
#define SMEM_MM (2 * BUFB)        // 81920

__device__ __forceinline__ void mm_stage(
    uint32_t sb, int buf,
    const __nv_bfloat16* __restrict__ Ah, const __nv_bfloat16* __restrict__ Al,
    const __nv_bfloat16* __restrict__ Bh, const __nv_bfloat16* __restrict__ Bl,
    int M, int K, int mBase, int nBase, int kc, int tid)
{
    uint32_t bb = sb + buf * BUFB;
#pragma unroll
    for (int c = 0; c < 8; c++) {
        int idx = c * 256 + tid;          // 0..2047
        int part = idx >> 9;              // 0..3
        int row  = (idx >> 2) & 127;
        int q    = idx & 3;
        const __nv_bfloat16* src = (part == 0) ? Ah : (part == 1) ? Al : (part == 2) ? Bh : Bl;
        int grow = (part < 2) ? min(mBase + row, M - 1) : (nBase + row);
        const void* g = src + (size_t)grow * K + kc * TCK + q * 8;
        uint32_t sa = bb + part * PARTB + row * ROWB + q * 16;
        cpa16(sa, g);
    }
    asm volatile("cp.async.commit_group;" ::: "memory");
}

template <int EPI>
__device__ void mm_body(const __nv_bfloat16* Ah, const __nv_bfloat16* Al,
                        const __nv_bfloat16* Bh, const __nv_bfloat16* Bl,
                        const float* bias, const float* res,
                        float* Cf, __nv_bfloat16* Ch, __nv_bfloat16* Cl,
                        int M, int N, int K, int mBase, int nBase)
{
    extern __shared__ char smem[];
    uint32_t sb = smem_u32(smem);
    const int tid = threadIdx.x;
    const int wid = tid >> 5, lane = tid & 31;
    const int wM = wid >> 2;          // 0..1 -> m offset *64
    const int wN = wid & 3;           // 0..3 -> n offset *32

    float acc[4][4][4];
#pragma unroll
    for (int mi = 0; mi < 4; mi++)
#pragma unroll
        for (int ni = 0; ni < 4; ni++)
#pragma unroll
            for (int r = 0; r < 4; r++) acc[mi][ni][r] = 0.f;

    const int NK = K / TCK;

    // per-thread ldmatrix smem offsets (element addressing within a part)
    const int ll = lane & 15;
    // A: row = wM*64 + mi*16 + (lane&15), kbyte = (ks + (lane>=16 ? 8:0))*2
    const uint32_t aRowOff = (uint32_t)(wM * 64 + ll) * ROWB + ((lane >> 4) << 4); // +16B if lane>=16
    // B: row = wN*32 + ni*8 + (ll&7), kbyte = (ks + ((ll>>3)&1)*8)*2
    const uint32_t bRowOff = (uint32_t)(wN * 32 + (ll & 7)) * ROWB + (((ll >> 3) & 1) << 4);

    mm_stage(sb, 0, Ah, Al, Bh, Bl, M, K, mBase, nBase, 0, tid);

    for (int kt = 0; kt < NK; kt++) {
        if (kt + 1 < NK) {
            mm_stage(sb, (kt + 1) & 1, Ah, Al, Bh, Bl, M, K, mBase, nBase, kt + 1, tid);
            asm volatile("cp.async.wait_group 1;" ::: "memory");
        } else {
            asm volatile("cp.async.wait_group 0;" ::: "memory");
        }
        __syncthreads();

        uint32_t bb = sb + (kt & 1) * BUFB;
        uint32_t As_hi = bb,             As_lo = bb + PARTB;
        uint32_t Bs_hi = bb + 2 * PARTB, Bs_lo = bb + 3 * PARTB;

#pragma unroll
        for (int ks = 0; ks < TCK; ks += 16) {
            uint32_t bh[4][2], bl[4][2];
#pragma unroll
            for (int ni = 0; ni < 4; ni++) {
                uint32_t off = (uint32_t)(ni * 8) * ROWB + bRowOff + (uint32_t)(ks * 2);
                ldsm_x2(bh[ni], Bs_hi + off);
                ldsm_x2(bl[ni], Bs_lo + off);
            }
#pragma unroll
            for (int mi = 0; mi < 4; mi++) {
                uint32_t off = (uint32_t)(mi * 16) * ROWB + aRowOff + (uint32_t)(ks * 2);
                uint32_t ah[4], al[4];
                ldsm_x4(ah, As_hi + off);
                ldsm_x4(al, As_lo + off);
#pragma unroll
                for (int ni = 0; ni < 4; ni++) {
                    mma_bf16(acc[mi][ni], ah, bh[ni]);
                    mma_bf16(acc[mi][ni], ah, bl[ni]);
                    mma_bf16(acc[mi][ni], al, bh[ni]);
                }
            }
        }
        __syncthreads();
    }

    // epilogue from registers
    const int g4 = lane >> 2, t4 = lane & 3;
#pragma unroll
    for (int mi = 0; mi < 4; mi++) {
        int r0 = mBase + wM * 64 + mi * 16 + g4;
        int r1 = r0 + 8;
#pragma unroll
        for (int ni = 0; ni < 4; ni++) {
            int c = nBase + wN * 32 + ni * 8 + t4 * 2;
            float b0 = bias[c], b1 = bias[c + 1];
#pragma unroll
            for (int half = 0; half < 2; half++) {
                int r = half ? r1 : r0;
                if (r >= M) continue;
                float v0 = acc[mi][ni][half * 2 + 0] + b0;
                float v1 = acc[mi][ni][half * 2 + 1] + b1;
                size_t o = (size_t)r * N + c;
                if (EPI == 3) {
                    float t0 = 0.5f * v0 * (1.0f + erff(v0 * 0.70710678118654752f));
                    float t1 = 0.5f * v1 * (1.0f + erff(v1 * 0.70710678118654752f));
                    __nv_bfloat16 h0, l0, h1, l1;
                    bsplit(t0, h0, l0);
                    bsplit(t1, h1, l1);
                    *(__nv_bfloat162*)(Ch + o) = __nv_bfloat162(h0, h1);
                    *(__nv_bfloat162*)(Cl + o) = __nv_bfloat162(l0, l1);
                } else if (EPI == 1) {
                    float2 rv = *(const float2*)(res + o);
                    *(float2*)(Cf + o) = make_float2(rv.x + v0, rv.y + v1);
                } else {
                    *(float2*)(Cf + o) = make_float2(v0, v1);
                }
            }
        }
    }
}

template <int EPI>
__global__ __launch_bounds__(256, 2)
void mm_gemm_k(const __nv_bfloat16* Ah, const __nv_bfloat16* Al,
               const __nv_bfloat16* Bh, const __nv_bfloat16* Bl,
               const float* bias, const float* res,
               float* Cf, __nv_bfloat16* Ch, __nv_bfloat16* Cl,
               int M, int N, int K)
{
    mm_body<EPI>(Ah, Al, Bh, Bl, bias, res, Cf, Ch, Cl, M, N, K,
                 blockIdx.y * TCM, blockIdx.x * TCN);
}

__global__ __launch_bounds__(256, 2)
void mm_qkv_k(const __nv_bfloat16* zh, const __nv_bfloat16* zl,
              const __nv_bfloat16* wqh, const __nv_bfloat16* wql,
              const __nv_bfloat16* wkh, const __nv_bfloat16* wkl,
              const __nv_bfloat16* wvh, const __nv_bfloat16* wvl,
              const float* bq, const float* bk, const float* bv,
              float* q, float* k, float* v)
{
    const __nv_bfloat16 *Bh, *Bl; const float* bias; float* out;
    if (blockIdx.z == 0)      { Bh = wqh; Bl = wql; bias = bq; out = q; }
    else if (blockIdx.z == 1) { Bh = wkh; Bl = wkl; bias = bk; out = k; }
    else                      { Bh = wvh; Bl = wvl; bias = bv; out = v; }
    mm_body<0>(zh, zl, Bh, Bl, bias, nullptr, out, nullptr, nullptr,
               MTOK, D_, D_, blockIdx.y * TCM, blockIdx.x * TCN);
}

// ---------------- weight transpose + split: W[K][N] -> T{h,l}[N][K] ----------------
__global__ void tsplit_k(const float* __restrict__ W,
                         __nv_bfloat16* __restrict__ Th, __nv_bfloat16* __restrict__ Tl,
                         int K, int N)
{
    __shared__ float t[32][33];
    int k0 = blockIdx.x * 32, n0 = blockIdx.y * 32;
    size_t mb = (size_t)blockIdx.z * K * N;
    const float* Wb = W + mb;
    for (int i = threadIdx.y; i < 32; i += 8)
        t[i][threadIdx.x] = Wb[(size_t)(k0 + i) * N + n0 + threadIdx.x];
    __syncthreads();
    for (int i = threadIdx.y; i < 32; i += 8) {
        float f = t[threadIdx.x][i];
        __nv_bfloat16 h, l;
        bsplit(f, h, l);
        size_t o = mb + (size_t)(n0 + i) * K + k0 + threadIdx.x;
        Th[o] = h;
        Tl[o] = l;
    }
}

// ---------------- block reduce ----------------
__device__ float blockReduceSum(float v)
{
    __shared__ float red[8];
    __syncthreads();
    int lane = threadIdx.x & 31, w = threadIdx.x >> 5;
#pragma unroll
    for (int o = 16; o; o >>= 1) v += __shfl_xor_sync(0xffffffffu, v, o);
    if (lane == 0) red[w] = v;
    __syncthreads();
    if (w == 0) {
        float r = (lane < 8) ? red[lane] : 0.f;
#pragma unroll
        for (int o = 4; o; o >>= 1) r += __shfl_xor_sync(0xffffffffu, r, o);
        if (lane == 0) red[0] = r;
    }
    __syncthreads();
    return red[0];
}

// ---------------- LayerNorm (eps OUTSIDE sqrt) -> bf16 hi/lo ----------------
__global__ void ln_split_k(const float* __restrict__ x, const float* __restrict__ w,
                           const float* __restrict__ b,
                           __nv_bfloat16* __restrict__ oh, __nv_bfloat16* __restrict__ ol)
{
    int row = blockIdx.x;
    const float* xr = x + (size_t)row * D_;
    __shared__ float sm[D_];
    float part = 0.f;
    for (int d = threadIdx.x; d < D_; d += blockDim.x) {
        float t = xr[d];
        sm[d] = t;
        part += t;
    }
    float mean = blockReduceSum(part) * (1.0f / D_);
    float p2 = 0.f;
    for (int d = threadIdx.x; d < D_; d += blockDim.x) {
        float t = sm[d] - mean;
        p2 += t * t;
    }
    float var = blockReduceSum(p2) * (1.0f / D_);
    float inv = 1.0f / (sqrtf(var) + 1e-5f);
    size_t base = (size_t)row * D_;
    for (int d = threadIdx.x; d < D_; d += blockDim.x) {
        float z = (sm[d] - mean) * inv * w[d] + b[d];
        __nv_bfloat16 h, l;
        bsplit(z, h, l);
        oh[base + d] = h;
        ol[base + d] = l;
    }
}

// fp32 LN (head)
__global__ void ln_k(const float* __restrict__ x, const float* __restrict__ w,
                     const float* __restrict__ b, float* __restrict__ out)
{
    int row = blockIdx.x;
    const float* xr = x + (size_t)row * D_;
    __shared__ float sm[D_];
    float part = 0.f;
    for (int d = threadIdx.x; d < D_; d += blockDim.x) {
        float t = xr[d];
        sm[d] = t;
        part += t;
    }
    float mean = blockReduceSum(part) * (1.0f / D_);
    float p2 = 0.f;
    for (int d = threadIdx.x; d < D_; d += blockDim.x) {
        float t = sm[d] - mean;
        p2 += t * t;
    }
    float var = blockReduceSum(p2) * (1.0f / D_);
    float inv = 1.0f / (sqrtf(var) + 1e-5f);
    float* orow = out + (size_t)row * D_;
    for (int d = threadIdx.x; d < D_; d += blockDim.x)
        orow[d] = (sm[d] - mean) * inv * w[d] + b[d];
}

// ---------------- patch gather -> bf16 hi/lo ----------------
__global__ void patch_split_k(const float* __restrict__ x,
                              __nv_bfloat16* __restrict__ Ah, __nv_bfloat16* __restrict__ Al)
{
    size_t idx = (size_t)blockIdx.x * 256 + threadIdx.x;
    if (idx >= (size_t)MPAT * D_) return;
    int kf = (int)(idx % D_);
    size_t r = idx / D_;
    int n = (int)(r % NP_);
    int b = (int)(r / NP_);
    int ph = n / 14, pw = n % 14;
    int c  = kf >> 8;
    int py = (kf >> 4) & 15;
    int px = kf & 15;
    float v = x[(((size_t)b * 3 + c) * 224 + (ph * 16 + py)) * 224 + (pw * 16 + px)];
    __nv_bfloat16 h, l;
    bsplit(v, h, l);
    Ah[idx] = h;
    Al[idx] = l;
}

// ---------------- assemble ----------------
__global__ void assemble_k(const float* __restrict__ pe, const float* __restrict__ cls,
                           const float* __restrict__ pos, float* __restrict__ h)
{
    size_t idx = (size_t)blockIdx.x * 256 + threadIdx.x;
    if (idx >= (size_t)MTOK * D_) return;
    int d = (int)(idx % D_);
    size_t r = idx / D_;
    int s = (int)(r % S_);
    int b = (int)(r / S_);
    float base = (s == 0) ? cls[d] : pe[((size_t)b * NP_ + (s - 1)) * D_ + d];
    h[idx] = base + pos[(size_t)s * D_ + d];
}

// ---------------- attention (SIMT, fp32) ----------------
__global__ void scores_k(const float* __restrict__ q, const float* __restrict__ kmat,
                         float* __restrict__ s)
{
    int bh = blockIdx.x;
    int b = bh / NH_, h = bh % NH_;
    int i0 = blockIdx.y * 16;

    __shared__ float qs[16][HD_];
    for (int idx = threadIdx.x; idx < 16 * HD_; idx += 256) {
        int ii = idx >> 6, d = idx & 63;
        int si = i0 + ii;
        qs[ii][d] = (si < S_) ? q[((size_t)(b * S_ + si)) * D_ + h * HD_ + d] : 0.f;
    }
    __syncthreads();

    for (int j = threadIdx.x; j < S_; j += 256) {
        const float* kr = kmat + ((size_t)(b * S_ + j)) * D_ + h * HD_;
        float acc[16];
#pragma unroll
        for (int ii = 0; ii < 16; ii++) acc[ii] = 0.f;
        for (int d = 0; d < HD_; d++) {
            float kv = kr[d];
#pragma unroll
            for (int ii = 0; ii < 16; ii++) acc[ii] += qs[ii][d] * kv;
        }
#pragma unroll
        for (int ii = 0; ii < 16; ii++) {
            int i = i0 + ii;
            if (i < S_) s[((size_t)bh * S_ + i) * S_ + j] = acc[ii] * 0.125f;
        }
    }
}

__global__ void softmax_k(float* __restrict__ s)
{
    int row = blockIdx.x * blockDim.y + threadIdx.y;
    if (row >= BH_ * S_) return;
    float* p = s + (size_t)row * S_;
    int lane = threadIdx.x;
    float buf[7];
    int cnt = 0;
    float m = -1e30f;
    for (int j = lane; j < S_; j += 32) {
        buf[cnt] = p[j];
        m = fmaxf(m, buf[cnt]);
        cnt++;
    }
#pragma unroll
    for (int o = 16; o; o >>= 1) m = fmaxf(m, __shfl_xor_sync(0xffffffffu, m, o));
    float sum = 0.f;
    cnt = 0;
    for (int j = lane; j < S_; j += 32) {
        float e = __expf(buf[cnt] - m);
        buf[cnt] = e;
        sum += e;
        cnt++;
    }
#pragma unroll
    for (int o = 16; o; o >>= 1) sum += __shfl_xor_sync(0xffffffffu, sum, o);
    float inv = 1.0f / sum;
    cnt = 0;
    for (int j = lane; j < S_; j += 32) p[j] = buf[cnt++] * inv;
}

// y = attn @ v -> bf16 hi/lo
__global__ void av_split_k(const float* __restrict__ s, const float* __restrict__ v,
                           __nv_bfloat16* __restrict__ yh, __nv_bfloat16* __restrict__ yl)
{
    int bh = blockIdx.x;
    int b = bh / NH_, h = bh % NH_;
    int i0 = blockIdx.y * 16;

    __shared__ float ps[16][S_];
    for (int idx = threadIdx.x; idx < 16 * S_; idx += 256) {
        int ii = idx / S_, j = idx % S_;
        int si = i0 + ii;
        ps[ii][j] = (si < S_) ? s[((size_t)bh * S_ + si) * S_ + j] : 0.f;
    }
    __syncthreads();

    int d = threadIdx.x & 63;
    int ig = threadIdx.x >> 6;
    float acc[4] = {0.f, 0.f, 0.f, 0.f};
    for (int j = 0; j < S_; j++) {
        float vv = v[((size_t)(b * S_ + j)) * D_ + h * HD_ + d];
#pragma unroll
        for (int t = 0; t < 4; t++) acc[t] += ps[ig + t * 4][j] * vv;
    }
#pragma unroll
    for (int t = 0; t < 4; t++) {
        int i = i0 + ig + t * 4;
        if (i < S_) {
            size_t o = ((size_t)(b * S_ + i)) * D_ + h * HD_ + d;
            __nv_bfloat16 hh, ll;
            bsplit(acc[t], hh, ll);
            yh[o] = hh;
            yl[o] = ll;
        }
    }
}

// ---------------- cls gather ----------------
__global__ void clsgather_k(const float* __restrict__ h, float* __restrict__ o)
{
    int idx = blockIdx.x * 256 + threadIdx.x;
    if (idx >= B_ * D_) return;
    int b = idx / D_, d = idx % D_;
    o[idx] = h[((size_t)b * S_) * D_ + d];
}

// ---------------- head GEMM (SIMT fp32, tiny) ----------------
#define BM 128
#define BN 128
#define BKK 8
#define TM 8
#define TN 8
__global__ __launch_bounds__(256)
void sgemm_head_k(const float* __restrict__ A, const float* __restrict__ B,
                  const float* __restrict__ bias, float* __restrict__ C,
                  int M, int N, int K)
{
    __shared__ float As[BKK][BM];
    __shared__ float Bs[BKK][BN];
    const int tid = threadIdx.x;
    const int mBase = blockIdx.y * BM;
    const int nBase = blockIdx.x * BN;
    const int aRow = tid >> 1;
    const int aCol = (tid & 1) * 4;
    const int bRow = tid >> 5;
    const int bCol = (tid & 31) * 4;
    const int tx = tid & 15;
    const int ty = tid >> 4;
    const int aRowG = min(mBase + aRow, M - 1);
    const int bColG = min(nBase + bCol, N - 4);

    float acc[TM][TN];
#pragma unroll
    for (int i = 0; i < TM; i++)
#pragma unroll
        for (int j = 0; j < TN; j++) acc[i][j] = 0.f;

    for (int k0 = 0; k0 < K; k0 += BKK) {
        float4 a4 = *(const float4*)(A + (size_t)aRowG * K + k0 + aCol);
        float4 b4 = *(const float4*)(B + (size_t)(k0 + bRow) * N + bColG);
        As[aCol + 0][aRow] = a4.x;
        As[aCol + 1][aRow] = a4.y;
        As[aCol + 2][aRow] = a4.z;
        As[aCol + 3][aRow] = a4.w;
        *(float4*)(&Bs[bRow][bCol]) = b4;
        __syncthreads();
#pragma unroll
        for (int kk = 0; kk < BKK; kk++) {
            float a_reg[TM], b_reg[TN];
#pragma unroll
            for (int i = 0; i < TM; i++) a_reg[i] = As[kk][ty * TM + i];
#pragma unroll
            for (int j = 0; j < TN; j++) b_reg[j] = Bs[kk][tx * TN + j];
#pragma unroll
            for (int i = 0; i < TM; i++)
#pragma unroll
                for (int j = 0; j < TN; j++)
                    acc[i][j] += a_reg[i] * b_reg[j];
        }
        __syncthreads();
    }
#pragma unroll
    for (int i = 0; i < TM; i++) {
        int r = mBase + ty * TM + i;
        if (r >= M) continue;
#pragma unroll
        for (int j = 0; j < TN; j++) {
            int c = nBase + tx * TN + j;
            if (c >= N) continue;
            C[(size_t)r * N + c] = acc[i][j] + bias[c];
        }
    }
}

// ---------------- host ----------------
template <typename T>
static T* symaddr(const void* sym_)
{
    void* p = nullptr;
    cudaGetSymbolAddress(&p, sym_);
    return (T*)p;
}

extern "C" void kernel_launch(void* const* d_in, const int* in_sizes, int n_in,
                              void* d_out, int out_size)
{
    const float* x         = (const float*)d_in[0];
    const float* patch_w   = (const float*)d_in[1];
    const float* patch_b   = (const float*)d_in[2];
    const float* cls_token = (const float*)d_in[3];
    const float* pos_emb   = (const float*)d_in[4];
    const float* ln1_w     = (const float*)d_in[5];
    const float* ln1_b     = (const float*)d_in[6];
    const float* wq        = (const float*)d_in[7];
    const float* bq        = (const float*)d_in[8];
    const float* wk        = (const float*)d_in[9];
    const float* bk        = (const float*)d_in[10];
    const float* wv        = (const float*)d_in[11];
    const float* bv        = (const float*)d_in[12];
    const float* wy        = (const float*)d_in[13];
    const float* by        = (const float*)d_in[14];
    const float* ln2_w     = (const float*)d_in[15];
    const float* ln2_b     = (const float*)d_in[16];
    const float* mlp_w1    = (const float*)d_in[17];
    const float* mlp_b1    = (const float*)d_in[18];
    const float* mlp_w2    = (const float*)d_in[19];
    const float* mlp_b2    = (const float*)d_in[20];
    const float* head_ln_w = (const float*)d_in[21];
    const float* head_ln_b = (const float*)d_in[22];
    const float* head_w    = (const float*)d_in[23];
    const float* head_b    = (const float*)d_in[24];

    float* pe    = symaddr<float>(g_pe);
    float* h     = symaddr<float>(g_h);
    float* q     = symaddr<float>(g_q);
    float* k     = symaddr<float>(g_k);
    float* v     = symaddr<float>(g_v);
    float* sc    = symaddr<float>(g_sc);
    float* cls   = symaddr<float>(g_cls);
    float* clsln = symaddr<float>(g_clsln);

    __nv_bfloat16* wq_h = symaddr<__nv_bfloat16>(g_wq_h);
    __nv_bfloat16* wq_l = symaddr<__nv_bfloat16>(g_wq_l);
    __nv_bfloat16* wk_h = symaddr<__nv_bfloat16>(g_wk_h);
    __nv_bfloat16* wk_l = symaddr<__nv_bfloat16>(g_wk_l);
    __nv_bfloat16* wv_h = symaddr<__nv_bfloat16>(g_wv_h);
    __nv_bfloat16* wv_l = symaddr<__nv_bfloat16>(g_wv_l);
    __nv_bfloat16* wy_h = symaddr<__nv_bfloat16>(g_wy_h);
    __nv_bfloat16* wy_l = symaddr<__nv_bfloat16>(g_wy_l);
    __nv_bfloat16* w1_h = symaddr<__nv_bfloat16>(g_w1_h);
    __nv_bfloat16* w1_l = symaddr<__nv_bfloat16>(g_w1_l);
    __nv_bfloat16* w2_h = symaddr<__nv_bfloat16>(g_w2_h);
    __nv_bfloat16* w2_l = symaddr<__nv_bfloat16>(g_w2_l);
    __nv_bfloat16* wp_h = symaddr<__nv_bfloat16>(g_wp_h);
    __nv_bfloat16* wp_l = symaddr<__nv_bfloat16>(g_wp_l);
    __nv_bfloat16* zh   = symaddr<__nv_bfloat16>(g_zh);
    __nv_bfloat16* zl   = symaddr<__nv_bfloat16>(g_zl);
    __nv_bfloat16* yh   = symaddr<__nv_bfloat16>(g_yh);
    __nv_bfloat16* yl   = symaddr<__nv_bfloat16>(g_yl);
    __nv_bfloat16* Ah   = symaddr<__nv_bfloat16>(g_Ah);
    __nv_bfloat16* Al   = symaddr<__nv_bfloat16>(g_Al);
    __nv_bfloat16* m1h  = symaddr<__nv_bfloat16>(g_m1h);
    __nv_bfloat16* m1l  = symaddr<__nv_bfloat16>(g_m1l);

    cudaFuncSetAttribute(mm_gemm_k<0>, cudaFuncAttributeMaxDynamicSharedMemorySize, SMEM_MM);
    cudaFuncSetAttribute(mm_gemm_k<1>, cudaFuncAttributeMaxDynamicSharedMemorySize, SMEM_MM);
    cudaFuncSetAttribute(mm_gemm_k<3>, cudaFuncAttributeMaxDynamicSharedMemorySize, SMEM_MM);
    cudaFuncSetAttribute(mm_qkv_k,     cudaFuncAttributeMaxDynamicSharedMemorySize, SMEM_MM);

    dim3 tsb(32, 8);
    tsplit_k<<<dim3(D_ / 32, D_ / 32, L_), tsb>>>(wq, wq_h, wq_l, D_, D_);
    tsplit_k<<<dim3(D_ / 32, D_ / 32, L_), tsb>>>(wk, wk_h, wk_l, D_, D_);
    tsplit_k<<<dim3(D_ / 32, D_ / 32, L_), tsb>>>(wv, wv_h, wv_l, D_, D_);
    tsplit_k<<<dim3(D_ / 32, D_ / 32, L_), tsb>>>(wy, wy_h, wy_l, D_, D_);
    tsplit_k<<<dim3(D_ / 32, FF_ / 32, L_), tsb>>>(mlp_w1, w1_h, w1_l, D_, FF_);
    tsplit_k<<<dim3(FF_ / 32, D_ / 32, L_), tsb>>>(mlp_w2, w2_h, w2_l, FF_, D_);
    tsplit_k<<<dim3(D_ / 32, D_ / 32, 1), tsb>>>(patch_w, wp_h, wp_l, D_, D_);

    // patch embed
    patch_split_k<<<(int)(((size_t)MPAT * D_ + 255) / 256), 256>>>(x, Ah, Al);
    mm_gemm_k<0><<<dim3(D_ / TCN, MPAT / TCM), 256, SMEM_MM>>>(
        Ah, Al, wp_h, wp_l, patch_b, nullptr, pe, nullptr, nullptr, MPAT, D_, D_);
    assemble_k<<<(int)(((size_t)MTOK * D_ + 255) / 256), 256>>>(pe, cls_token, pos_emb, h);

    const int MT = (MTOK + TCM - 1) / TCM;  // 50
    const int sm_rows = BH_ * S_;
    for (int l = 0; l < L_; l++) {
        size_t wo  = (size_t)l * D_ * D_;
        size_t w1o = (size_t)l * D_ * FF_;
        size_t w2o = (size_t)l * FF_ * D_;

        ln_split_k<<<MTOK, 256>>>(h, ln1_w + (size_t)l * D_, ln1_b + (size_t)l * D_, zh, zl);

        mm_qkv_k<<<dim3(D_ / TCN, MT, 3), 256, SMEM_MM>>>(
            zh, zl,
            wq_h + wo, wq_l + wo, wk_h + wo, wk_l + wo, wv_h + wo, wv_l + wo,
            bq + (size_t)l * D_, bk + (size_t)l * D_, bv + (size_t)l * D_,
            q, k, v);

        scores_k<<<dim3(BH_, (S_ + 15) / 16), 256>>>(q, k, sc);
        softmax_k<<<(sm_rows + 7) / 8, dim3(32, 8)>>>(sc);
        av_split_k<<<dim3(BH_, (S_ + 15) / 16), 256>>>(sc, v, yh, yl);

        mm_gemm_k<1><<<dim3(D_ / TCN, MT), 256, SMEM_MM>>>(
            yh, yl, wy_h + wo, wy_l + wo, by + (size_t)l * D_, h, h, nullptr, nullptr,
            MTOK, D_, D_);

        ln_split_k<<<MTOK, 256>>>(h, ln2_w + (size_t)l * D_, ln2_b + (size_t)l * D_, zh, zl);

        mm_gemm_k<3><<<dim3(FF_ / TCN, MT), 256, SMEM_MM>>>(
            zh, zl, w1_h + w1o, w1_l + w1o, mlp_b1 + (size_t)l * FF_, nullptr,
            nullptr, m1h, m1l, MTOK, FF_, D_);

        mm_gemm_k<1><<<dim3(D_ / TCN, MT), 256, SMEM_MM>>>(
            m1h, m1l, w2_h + w2o, w2_l + w2o, mlp_b2 + (size_t)l * D_, h, h,
            nullptr, nullptr, MTOK, D_, FF_);
    }

    // head
    clsgather_k<<<(B_ * D_ + 255) / 256, 256>>>(h, cls);
    ln_k<<<B_, 256>>>(cls, head_ln_w, head_ln_b, clsln);
    sgemm_head_k<<<dim3((NC_ + BN - 1) / BN, (B_ + BM - 1) / BM), 256>>>(
        clsln, head_w, head_b, (float*)d_out, B_, NC_, D_);
}

// round 8
// speedup vs baseline: 2.8826x; 1.1885x over previous
#include <cuda_runtime.h>
#include <cuda_bf16.h>
#include <math.h>
#include <stddef.h>
#include <stdint.h>

// ---------------- problem constants ----------------
#define B_   32
#define S_   197
#define D_   768
#define L_   12
#define FF_  3072
#define NH_  12
#define HD_  64
#define NC_  1000
#define NP_  196
#define MTOK (B_ * S_)    // 6304
#define MPAT (B_ * NP_)   // 6272
#define BH_  (B_ * NH_)   // 384

// ---------------- fp32 scratch ----------------
__device__ float g_pe  [(size_t)MPAT * D_];
__device__ float g_h   [(size_t)MTOK * D_];
__device__ float g_cls [B_ * D_];
__device__ float g_clsln[B_ * D_];

// ---------------- bf16 hi/lo scratch ----------------
__device__ __nv_bfloat16 g_wq_h[(size_t)L_*D_*D_],  g_wq_l[(size_t)L_*D_*D_];
__device__ __nv_bfloat16 g_wk_h[(size_t)L_*D_*D_],  g_wk_l[(size_t)L_*D_*D_];
__device__ __nv_bfloat16 g_wv_h[(size_t)L_*D_*D_],  g_wv_l[(size_t)L_*D_*D_];
__device__ __nv_bfloat16 g_wy_h[(size_t)L_*D_*D_],  g_wy_l[(size_t)L_*D_*D_];
__device__ __nv_bfloat16 g_w1_h[(size_t)L_*D_*FF_], g_w1_l[(size_t)L_*D_*FF_];
__device__ __nv_bfloat16 g_w2_h[(size_t)L_*FF_*D_], g_w2_l[(size_t)L_*FF_*D_];
__device__ __nv_bfloat16 g_wp_h[(size_t)D_*D_],     g_wp_l[(size_t)D_*D_];
__device__ __nv_bfloat16 g_zh[(size_t)MTOK*D_],   g_zl[(size_t)MTOK*D_];
__device__ __nv_bfloat16 g_yh[(size_t)MTOK*D_],   g_yl[(size_t)MTOK*D_];
__device__ __nv_bfloat16 g_Ah[(size_t)MPAT*D_],   g_Al[(size_t)MPAT*D_];
__device__ __nv_bfloat16 g_m1h[(size_t)MTOK*FF_], g_m1l[(size_t)MTOK*FF_];
// qkv in split form
__device__ __nv_bfloat16 g_qh[(size_t)MTOK*D_], g_ql[(size_t)MTOK*D_];
__device__ __nv_bfloat16 g_kh[(size_t)MTOK*D_], g_kl[(size_t)MTOK*D_];
__device__ __nv_bfloat16 g_vh[(size_t)MTOK*D_], g_vl[(size_t)MTOK*D_];

// ---------------- PTX helpers ----------------
__device__ __forceinline__ uint32_t smem_u32(const void* p) {
    uint32_t a;
    asm("{ .reg .u64 t; cvta.to.shared.u64 t, %1; cvt.u32.u64 %0, t; }" : "=r"(a) : "l"(p));
    return a;
}
__device__ __forceinline__ void cpa16(uint32_t saddr, const void* g) {
    asm volatile("cp.async.cg.shared.global [%0], [%1], 16;" :: "r"(saddr), "l"(g));
}
__device__ __forceinline__ void ldsm_x4(uint32_t* r, uint32_t a) {
    asm volatile("ldmatrix.sync.aligned.m8n8.x4.shared.b16 {%0,%1,%2,%3}, [%4];"
                 : "=r"(r[0]), "=r"(r[1]), "=r"(r[2]), "=r"(r[3]) : "r"(a));
}
__device__ __forceinline__ void ldsm_x2(uint32_t* r, uint32_t a) {
    asm volatile("ldmatrix.sync.aligned.m8n8.x2.shared.b16 {%0,%1}, [%2];"
                 : "=r"(r[0]), "=r"(r[1]) : "r"(a));
}
__device__ __forceinline__ void mma_bf16(float* c, const uint32_t* a, const uint32_t* b) {
    asm volatile(
        "mma.sync.aligned.m16n8k16.row.col.f32.bf16.bf16.f32 "
        "{%0,%1,%2,%3}, {%4,%5,%6,%7}, {%8,%9}, {%0,%1,%2,%3};"
        : "+f"(c[0]), "+f"(c[1]), "+f"(c[2]), "+f"(c[3])
        : "r"(a[0]), "r"(a[1]), "r"(a[2]), "r"(a[3]), "r"(b[0]), "r"(b[1]));
}
__device__ __forceinline__ void bsplit(float f, __nv_bfloat16& h, __nv_bfloat16& l) {
    h = __float2bfloat16_rn(f);
    l = __float2bfloat16_rn(f - __bfloat162float(h));
}
__device__ __forceinline__ uint32_t pack2(__nv_bfloat16 a, __nv_bfloat16 b) {
    __nv_bfloat162 t(a, b);
    return *(uint32_t*)&t;
}

// ======================================================================
// bf16x3 mma.sync GEMM (unchanged from R7 except EPI 4)
// EPI: 0 bias->f32, 1 bias+res->f32, 3 bias+GELU->bf16 hi/lo, 4 bias->bf16 hi/lo
// ======================================================================
#define TCM 128
#define TCN 128
#define TCK 32
#define ROWB 80
#define PARTB (128 * ROWB)
#define BUFB  (4 * PARTB)
#define SMEM_MM (2 * BUFB)

__device__ __forceinline__ void mm_stage(
    uint32_t sb, int buf,
    const __nv_bfloat16* __restrict__ Ah, const __nv_bfloat16* __restrict__ Al,
    const __nv_bfloat16* __restrict__ Bh, const __nv_bfloat16* __restrict__ Bl,
    int M, int K, int mBase, int nBase, int kc, int tid)
{
    uint32_t bb = sb + buf * BUFB;
#pragma unroll
    for (int c = 0; c < 8; c++) {
        int idx = c * 256 + tid;
        int part = idx >> 9;
        int row  = (idx >> 2) & 127;
        int q    = idx & 3;
        const __nv_bfloat16* src = (part == 0) ? Ah : (part == 1) ? Al : (part == 2) ? Bh : Bl;
        int grow = (part < 2) ? min(mBase + row, M - 1) : (nBase + row);
        const void* g = src + (size_t)grow * K + kc * TCK + q * 8;
        uint32_t sa = bb + part * PARTB + row * ROWB + q * 16;
        cpa16(sa, g);
    }
    asm volatile("cp.async.commit_group;" ::: "memory");
}

template <int EPI>
__device__ void mm_body(const __nv_bfloat16* Ah, const __nv_bfloat16* Al,
                        const __nv_bfloat16* Bh, const __nv_bfloat16* Bl,
                        const float* bias, const float* res,
                        float* Cf, __nv_bfloat16* Ch, __nv_bfloat16* Cl,
                        int M, int N, int K, int mBase, int nBase)
{
    extern __shared__ char smem[];
    uint32_t sb = smem_u32(smem);
    const int tid = threadIdx.x;
    const int wid = tid >> 5, lane = tid & 31;
    const int wM = wid >> 2;
    const int wN = wid & 3;

    float acc[4][4][4];
#pragma unroll
    for (int mi = 0; mi < 4; mi++)
#pragma unroll
        for (int ni = 0; ni < 4; ni++)
#pragma unroll
            for (int r = 0; r < 4; r++) acc[mi][ni][r] = 0.f;

    const int NK = K / TCK;
    const int ll = lane & 15;
    const uint32_t aRowOff = (uint32_t)(wM * 64 + ll) * ROWB + ((lane >> 4) << 4);
    const uint32_t bRowOff = (uint32_t)(wN * 32 + (ll & 7)) * ROWB + (((ll >> 3) & 1) << 4);

    mm_stage(sb, 0, Ah, Al, Bh, Bl, M, K, mBase, nBase, 0, tid);

    for (int kt = 0; kt < NK; kt++) {
        if (kt + 1 < NK) {
            mm_stage(sb, (kt + 1) & 1, Ah, Al, Bh, Bl, M, K, mBase, nBase, kt + 1, tid);
            asm volatile("cp.async.wait_group 1;" ::: "memory");
        } else {
            asm volatile("cp.async.wait_group 0;" ::: "memory");
        }
        __syncthreads();

        uint32_t bb = sb + (kt & 1) * BUFB;
        uint32_t As_hi = bb,             As_lo = bb + PARTB;
        uint32_t Bs_hi = bb + 2 * PARTB, Bs_lo = bb + 3 * PARTB;

#pragma unroll
        for (int ks = 0; ks < TCK; ks += 16) {
            uint32_t bh[4][2], bl[4][2];
#pragma unroll
            for (int ni = 0; ni < 4; ni++) {
                uint32_t off = (uint32_t)(ni * 8) * ROWB + bRowOff + (uint32_t)(ks * 2);
                ldsm_x2(bh[ni], Bs_hi + off);
                ldsm_x2(bl[ni], Bs_lo + off);
            }
#pragma unroll
            for (int mi = 0; mi < 4; mi++) {
                uint32_t off = (uint32_t)(mi * 16) * ROWB + aRowOff + (uint32_t)(ks * 2);
                uint32_t ah[4], al[4];
                ldsm_x4(ah, As_hi + off);
                ldsm_x4(al, As_lo + off);
#pragma unroll
                for (int ni = 0; ni < 4; ni++) {
                    mma_bf16(acc[mi][ni], ah, bh[ni]);
                    mma_bf16(acc[mi][ni], ah, bl[ni]);
                    mma_bf16(acc[mi][ni], al, bh[ni]);
                }
            }
        }
        __syncthreads();
    }

    const int g4 = lane >> 2, t4 = lane & 3;
#pragma unroll
    for (int mi = 0; mi < 4; mi++) {
        int r0 = mBase + wM * 64 + mi * 16 + g4;
        int r1 = r0 + 8;
#pragma unroll
        for (int ni = 0; ni < 4; ni++) {
            int c = nBase + wN * 32 + ni * 8 + t4 * 2;
            float b0 = bias[c], b1 = bias[c + 1];
#pragma unroll
            for (int half = 0; half < 2; half++) {
                int r = half ? r1 : r0;
                if (r >= M) continue;
                float v0 = acc[mi][ni][half * 2 + 0] + b0;
                float v1 = acc[mi][ni][half * 2 + 1] + b1;
                size_t o = (size_t)r * N + c;
                if (EPI == 3 || EPI == 4) {
                    float t0 = v0, t1 = v1;
                    if (EPI == 3) {
                        t0 = 0.5f * v0 * (1.0f + erff(v0 * 0.70710678118654752f));
                        t1 = 0.5f * v1 * (1.0f + erff(v1 * 0.70710678118654752f));
                    }
                    __nv_bfloat16 h0, l0, h1, l1;
                    bsplit(t0, h0, l0);
                    bsplit(t1, h1, l1);
                    *(__nv_bfloat162*)(Ch + o) = __nv_bfloat162(h0, h1);
                    *(__nv_bfloat162*)(Cl + o) = __nv_bfloat162(l0, l1);
                } else if (EPI == 1) {
                    float2 rv = *(const float2*)(res + o);
                    *(float2*)(Cf + o) = make_float2(rv.x + v0, rv.y + v1);
                } else {
                    *(float2*)(Cf + o) = make_float2(v0, v1);
                }
            }
        }
    }
}

template <int EPI>
__global__ __launch_bounds__(256, 2)
void mm_gemm_k(const __nv_bfloat16* Ah, const __nv_bfloat16* Al,
               const __nv_bfloat16* Bh, const __nv_bfloat16* Bl,
               const float* bias, const float* res,
               float* Cf, __nv_bfloat16* Ch, __nv_bfloat16* Cl,
               int M, int N, int K)
{
    mm_body<EPI>(Ah, Al, Bh, Bl, bias, res, Cf, Ch, Cl, M, N, K,
                 blockIdx.y * TCM, blockIdx.x * TCN);
}

// fused QKV -> bf16 hi/lo outputs
__global__ __launch_bounds__(256, 2)
void mm_qkv_k(const __nv_bfloat16* zh, const __nv_bfloat16* zl,
              const __nv_bfloat16* wqh, const __nv_bfloat16* wql,
              const __nv_bfloat16* wkh, const __nv_bfloat16* wkl,
              const __nv_bfloat16* wvh, const __nv_bfloat16* wvl,
              const float* bq, const float* bk, const float* bv,
              __nv_bfloat16* qh, __nv_bfloat16* ql,
              __nv_bfloat16* kh, __nv_bfloat16* kl,
              __nv_bfloat16* vh, __nv_bfloat16* vl)
{
    const __nv_bfloat16 *Bh, *Bl; const float* bias;
    __nv_bfloat16 *Ch, *Cl;
    if (blockIdx.z == 0)      { Bh = wqh; Bl = wql; bias = bq; Ch = qh; Cl = ql; }
    else if (blockIdx.z == 1) { Bh = wkh; Bl = wkl; bias = bk; Ch = kh; Cl = kl; }
    else                      { Bh = wvh; Bl = wvl; bias = bv; Ch = vh; Cl = vl; }
    mm_body<4>(zh, zl, Bh, Bl, bias, nullptr, nullptr, Ch, Cl,
               MTOK, D_, D_, blockIdx.y * TCM, blockIdx.x * TCN);
}

// ======================================================================
// Fused tensor-core attention, one block per (bh, 64-query tile).
// Phase 1: S = Q K^T / 8 (bf16x3) -> smem fp32 [64][210]
// Phase 2: softmax rows in smem
// Phase 3: Y = P V (P split in-register, V^T staged in smem) -> yh/yl
// ======================================================================
#define AROW 144           // 72 bf16 per row (64 data + 8 pad)
#define ASC  210           // scores stride (fp32)
#define OQH 0
#define OQL 9216
#define OKH 18432
#define OKL 27648
#define OSC 36864
#define ATT_SMEM (OSC + 64 * ASC * 4)   // 90624

__global__ __launch_bounds__(256, 2)
void attn_k(const __nv_bfloat16* __restrict__ qh, const __nv_bfloat16* __restrict__ ql,
            const __nv_bfloat16* __restrict__ kh, const __nv_bfloat16* __restrict__ kl,
            const __nv_bfloat16* __restrict__ vh, const __nv_bfloat16* __restrict__ vl,
            __nv_bfloat16* __restrict__ yh, __nv_bfloat16* __restrict__ yl)
{
    extern __shared__ char smem[];
    uint32_t sb = smem_u32(smem);
    float* ssc = (float*)(smem + OSC);

    const int tid = threadIdx.x, wid = tid >> 5, lane = tid & 31;
    const int g4 = lane >> 2, t4 = lane & 3, ll = lane & 15;
    const int wM = wid >> 1;      // 0..3 -> 16 query rows
    const int wN = wid & 1;       // 0..1 -> 32 cols
    const int bh = blockIdx.y, b = bh / NH_, hd = bh % NH_;
    const int q0 = blockIdx.x * 64;
    const size_t base = (size_t)b * S_ * D_ + (size_t)hd * HD_;

    // ---- load Q tile (hi/lo) ----
    for (int idx = tid; idx < 4096; idx += 256) {
        int r = idx >> 6, d = idx & 63;
        size_t go = base + (size_t)min(q0 + r, S_ - 1) * D_ + d;
        *(__nv_bfloat16*)(smem + OQH + r * AROW + d * 2) = qh[go];
        *(__nv_bfloat16*)(smem + OQL + r * AROW + d * 2) = ql[go];
    }

    const uint32_t aQ = (uint32_t)(wM * 16 + ll) * AROW + ((lane >> 4) << 4);
    const uint32_t bOffBase = (uint32_t)((ll & 7)) * AROW + (((ll >> 3) & 1) << 4);

    // ---- scores ----
    for (int kt = 0; kt < 4; kt++) {
        for (int idx = tid; idx < 4096; idx += 256) {
            int r = idx >> 6, d = idx & 63;
            size_t go = base + (size_t)min(kt * 64 + r, S_ - 1) * D_ + d;
            *(__nv_bfloat16*)(smem + OKH + r * AROW + d * 2) = kh[go];
            *(__nv_bfloat16*)(smem + OKL + r * AROW + d * 2) = kl[go];
        }
        __syncthreads();

        float acc[4][4];
#pragma unroll
        for (int ni = 0; ni < 4; ni++)
#pragma unroll
            for (int r = 0; r < 4; r++) acc[ni][r] = 0.f;

#pragma unroll
        for (int ks = 0; ks < 4; ks++) {
            uint32_t kb = (uint32_t)(ks * 32);
            uint32_t aH[4], aL[4];
            ldsm_x4(aH, sb + OQH + aQ + kb);
            ldsm_x4(aL, sb + OQL + aQ + kb);
#pragma unroll
            for (int ni = 0; ni < 4; ni++) {
                uint32_t bo = (uint32_t)(wN * 32 + ni * 8) * AROW + bOffBase + kb;
                uint32_t bH[2], bL[2];
                ldsm_x2(bH, sb + OKH + bo);
                ldsm_x2(bL, sb + OKL + bo);
                mma_bf16(acc[ni], aH, bH);
                mma_bf16(acc[ni], aH, bL);
                mma_bf16(acc[ni], aL, bH);
            }
        }
        // store scores (scaled, masked)
#pragma unroll
        for (int ni = 0; ni < 4; ni++) {
            int colb = wN * 32 + ni * 8 + t4 * 2;
            int gc = kt * 64 + colb;
#pragma unroll
            for (int half = 0; half < 2; half++) {
                int rl = wM * 16 + g4 + half * 8;
                float v0 = acc[ni][half * 2 + 0] * 0.125f;
                float v1 = acc[ni][half * 2 + 1] * 0.125f;
                if (gc     >= S_) v0 = -1e30f;
                if (gc + 1 >= S_) v1 = -1e30f;
                if (gc < ASC)
                    *(float2*)(ssc + rl * ASC + gc) = make_float2(v0, v1);
            }
        }
        __syncthreads();
    }

    // ---- softmax (one warp per 8 rows) ----
    for (int rr = wid; rr < 64; rr += 8) {
        float* pr = ssc + rr * ASC;
        float m = -1e30f;
        for (int j = lane; j < ASC; j += 32) m = fmaxf(m, pr[j]);
#pragma unroll
        for (int o = 16; o; o >>= 1) m = fmaxf(m, __shfl_xor_sync(0xffffffffu, m, o));
        float s = 0.f;
        for (int j = lane; j < ASC; j += 32) {
            float e = __expf(pr[j] - m);
            pr[j] = e;
            s += e;
        }
#pragma unroll
        for (int o = 16; o; o >>= 1) s += __shfl_xor_sync(0xffffffffu, s, o);
        float inv = 1.0f / s;
        for (int j = lane; j < ASC; j += 32) pr[j] *= inv;
    }
    __syncthreads();

    // ---- PV ----
    float ya[4][4];
#pragma unroll
    for (int ni = 0; ni < 4; ni++)
#pragma unroll
        for (int r = 0; r < 4; r++) ya[ni][r] = 0.f;

    for (int kt = 0; kt < 4; kt++) {
        // stage V^T (rows = d, cols = local j), zero-masked beyond S
        for (int idx = tid; idx < 4096; idx += 256) {
            int j = idx >> 6, d = idx & 63;
            int jg = kt * 64 + j;
            size_t go = base + (size_t)min(jg, S_ - 1) * D_ + d;
            __nv_bfloat16 hv = (jg < S_) ? vh[go] : __float2bfloat16(0.f);
            __nv_bfloat16 lv = (jg < S_) ? vl[go] : __float2bfloat16(0.f);
            *(__nv_bfloat16*)(smem + OQH + d * AROW + j * 2) = hv;
            *(__nv_bfloat16*)(smem + OQL + d * AROW + j * 2) = lv;
        }
        __syncthreads();

#pragma unroll
        for (int ks = 0; ks < 4; ks++) {
            // manual P fragment from fp32 smem (cols >= ASC -> 0)
            int r0 = wM * 16 + g4;
            int c0 = kt * 64 + ks * 16 + t4 * 2;
            float p[8];
            p[0] = (c0     < ASC) ? ssc[r0 * ASC + c0]           : 0.f;
            p[1] = (c0 + 1 < ASC) ? ssc[r0 * ASC + c0 + 1]       : 0.f;
            p[2] = (c0     < ASC) ? ssc[(r0 + 8) * ASC + c0]     : 0.f;
            p[3] = (c0 + 1 < ASC) ? ssc[(r0 + 8) * ASC + c0 + 1] : 0.f;
            p[4] = (c0 + 8 < ASC) ? ssc[r0 * ASC + c0 + 8]       : 0.f;
            p[5] = (c0 + 9 < ASC) ? ssc[r0 * ASC + c0 + 9]       : 0.f;
            p[6] = (c0 + 8 < ASC) ? ssc[(r0 + 8) * ASC + c0 + 8] : 0.f;
            p[7] = (c0 + 9 < ASC) ? ssc[(r0 + 8) * ASC + c0 + 9] : 0.f;
            __nv_bfloat16 ph[8], pl[8];
#pragma unroll
            for (int i = 0; i < 8; i++) bsplit(p[i], ph[i], pl[i]);
            uint32_t aH[4], aL[4];
            aH[0] = pack2(ph[0], ph[1]); aL[0] = pack2(pl[0], pl[1]);
            aH[1] = pack2(ph[2], ph[3]); aL[1] = pack2(pl[2], pl[3]);
            aH[2] = pack2(ph[4], ph[5]); aL[2] = pack2(pl[4], pl[5]);
            aH[3] = pack2(ph[6], ph[7]); aL[3] = pack2(pl[6], pl[7]);

            uint32_t kb = (uint32_t)(ks * 32);
#pragma unroll
            for (int ni = 0; ni < 4; ni++) {
                uint32_t bo = (uint32_t)(wN * 32 + ni * 8) * AROW + bOffBase + kb;
                uint32_t bH[2], bL[2];
                ldsm_x2(bH, sb + OQH + bo);
                ldsm_x2(bL, sb + OQL + bo);
                mma_bf16(ya[ni], aH, bH);
                mma_bf16(ya[ni], aH, bL);
                mma_bf16(ya[ni], aL, bH);
            }
        }
        __syncthreads();
    }

    // ---- epilogue: write y as bf16 hi/lo ----
#pragma unroll
    for (int ni = 0; ni < 4; ni++) {
        int d = wN * 32 + ni * 8 + t4 * 2;
#pragma unroll
        for (int half = 0; half < 2; half++) {
            int qrow = q0 + wM * 16 + g4 + half * 8;
            if (qrow >= S_) continue;
            size_t go = base + (size_t)qrow * D_ + d;
            __nv_bfloat16 h0, l0, h1, l1;
            bsplit(ya[ni][half * 2 + 0], h0, l0);
            bsplit(ya[ni][half * 2 + 1], h1, l1);
            *(__nv_bfloat162*)(yh + go) = __nv_bfloat162(h0, h1);
            *(__nv_bfloat162*)(yl + go) = __nv_bfloat162(l0, l1);
        }
    }
}

// ---------------- weight transpose + split ----------------
__global__ void tsplit_k(const float* __restrict__ W,
                         __nv_bfloat16* __restrict__ Th, __nv_bfloat16* __restrict__ Tl,
                         int K, int N)
{
    __shared__ float t[32][33];
    int k0 = blockIdx.x * 32, n0 = blockIdx.y * 32;
    size_t mb = (size_t)blockIdx.z * K * N;
    const float* Wb = W + mb;
    for (int i = threadIdx.y; i < 32; i += 8)
        t[i][threadIdx.x] = Wb[(size_t)(k0 + i) * N + n0 + threadIdx.x];
    __syncthreads();
    for (int i = threadIdx.y; i < 32; i += 8) {
        float f = t[threadIdx.x][i];
        __nv_bfloat16 h, l;
        bsplit(f, h, l);
        size_t o = mb + (size_t)(n0 + i) * K + k0 + threadIdx.x;
        Th[o] = h;
        Tl[o] = l;
    }
}

// ---------------- block reduce ----------------
__device__ float blockReduceSum(float v)
{
    __shared__ float red[8];
    __syncthreads();
    int lane = threadIdx.x & 31, w = threadIdx.x >> 5;
#pragma unroll
    for (int o = 16; o; o >>= 1) v += __shfl_xor_sync(0xffffffffu, v, o);
    if (lane == 0) red[w] = v;
    __syncthreads();
    if (w == 0) {
        float r = (lane < 8) ? red[lane] : 0.f;
#pragma unroll
        for (int o = 4; o; o >>= 1) r += __shfl_xor_sync(0xffffffffu, r, o);
        if (lane == 0) red[0] = r;
    }
    __syncthreads();
    return red[0];
}

// ---------------- LayerNorm (eps OUTSIDE sqrt) -> bf16 hi/lo ----------------
__global__ void ln_split_k(const float* __restrict__ x, const float* __restrict__ w,
                           const float* __restrict__ b,
                           __nv_bfloat16* __restrict__ oh, __nv_bfloat16* __restrict__ ol)
{
    int row = blockIdx.x;
    const float* xr = x + (size_t)row * D_;
    __shared__ float sm[D_];
    float part = 0.f;
    for (int d = threadIdx.x; d < D_; d += blockDim.x) {
        float t = xr[d];
        sm[d] = t;
        part += t;
    }
    float mean = blockReduceSum(part) * (1.0f / D_);
    float p2 = 0.f;
    for (int d = threadIdx.x; d < D_; d += blockDim.x) {
        float t = sm[d] - mean;
        p2 += t * t;
    }
    float var = blockReduceSum(p2) * (1.0f / D_);
    float inv = 1.0f / (sqrtf(var) + 1e-5f);
    size_t base = (size_t)row * D_;
    for (int d = threadIdx.x; d < D_; d += blockDim.x) {
        float z = (sm[d] - mean) * inv * w[d] + b[d];
        __nv_bfloat16 h, l;
        bsplit(z, h, l);
        oh[base + d] = h;
        ol[base + d] = l;
    }
}

// fp32 LN (head)
__global__ void ln_k(const float* __restrict__ x, const float* __restrict__ w,
                     const float* __restrict__ b, float* __restrict__ out)
{
    int row = blockIdx.x;
    const float* xr = x + (size_t)row * D_;
    __shared__ float sm[D_];
    float part = 0.f;
    for (int d = threadIdx.x; d < D_; d += blockDim.x) {
        float t = xr[d];
        sm[d] = t;
        part += t;
    }
    float mean = blockReduceSum(part) * (1.0f / D_);
    float p2 = 0.f;
    for (int d = threadIdx.x; d < D_; d += blockDim.x) {
        float t = sm[d] - mean;
        p2 += t * t;
    }
    float var = blockReduceSum(p2) * (1.0f / D_);
    float inv = 1.0f / (sqrtf(var) + 1e-5f);
    float* orow = out + (size_t)row * D_;
    for (int d = threadIdx.x; d < D_; d += blockDim.x)
        orow[d] = (sm[d] - mean) * inv * w[d] + b[d];
}

// ---------------- patch gather -> bf16 hi/lo ----------------
__global__ void patch_split_k(const float* __restrict__ x,
                              __nv_bfloat16* __restrict__ Ah, __nv_bfloat16* __restrict__ Al)
{
    size_t idx = (size_t)blockIdx.x * 256 + threadIdx.x;
    if (idx >= (size_t)MPAT * D_) return;
    int kf = (int)(idx % D_);
    size_t r = idx / D_;
    int n = (int)(r % NP_);
    int b = (int)(r / NP_);
    int ph = n / 14, pw = n % 14;
    int c  = kf >> 8;
    int py = (kf >> 4) & 15;
    int px = kf & 15;
    float v = x[(((size_t)b * 3 + c) * 224 + (ph * 16 + py)) * 224 + (pw * 16 + px)];
    __nv_bfloat16 h, l;
    bsplit(v, h, l);
    Ah[idx] = h;
    Al[idx] = l;
}

// ---------------- assemble ----------------
__global__ void assemble_k(const float* __restrict__ pe, const float* __restrict__ cls,
                           const float* __restrict__ pos, float* __restrict__ h)
{
    size_t idx = (size_t)blockIdx.x * 256 + threadIdx.x;
    if (idx >= (size_t)MTOK * D_) return;
    int d = (int)(idx % D_);
    size_t r = idx / D_;
    int s = (int)(r % S_);
    int b = (int)(r / S_);
    float base = (s == 0) ? cls[d] : pe[((size_t)b * NP_ + (s - 1)) * D_ + d];
    h[idx] = base + pos[(size_t)s * D_ + d];
}

// ---------------- cls gather ----------------
__global__ void clsgather_k(const float* __restrict__ h, float* __restrict__ o)
{
    int idx = blockIdx.x * 256 + threadIdx.x;
    if (idx >= B_ * D_) return;
    int b = idx / D_, d = idx % D_;
    o[idx] = h[((size_t)b * S_) * D_ + d];
}

// ---------------- head GEMM (SIMT fp32, tiny) ----------------
#define BM 128
#define BN 128
#define BKK 8
#define TM 8
#define TN 8
__global__ __launch_bounds__(256)
void sgemm_head_k(const float* __restrict__ A, const float* __restrict__ B,
                  const float* __restrict__ bias, float* __restrict__ C,
                  int M, int N, int K)
{
    __shared__ float As[BKK][BM];
    __shared__ float Bs[BKK][BN];
    const int tid = threadIdx.x;
    const int mBase = blockIdx.y * BM;
    const int nBase = blockIdx.x * BN;
    const int aRow = tid >> 1;
    const int aCol = (tid & 1) * 4;
    const int bRow = tid >> 5;
    const int bCol = (tid & 31) * 4;
    const int tx = tid & 15;
    const int ty = tid >> 4;
    const int aRowG = min(mBase + aRow, M - 1);
    const int bColG = min(nBase + bCol, N - 4);

    float acc[TM][TN];
#pragma unroll
    for (int i = 0; i < TM; i++)
#pragma unroll
        for (int j = 0; j < TN; j++) acc[i][j] = 0.f;

    for (int k0 = 0; k0 < K; k0 += BKK) {
        float4 a4 = *(const float4*)(A + (size_t)aRowG * K + k0 + aCol);
        float4 b4 = *(const float4*)(B + (size_t)(k0 + bRow) * N + bColG);
        As[aCol + 0][aRow] = a4.x;
        As[aCol + 1][aRow] = a4.y;
        As[aCol + 2][aRow] = a4.z;
        As[aCol + 3][aRow] = a4.w;
        *(float4*)(&Bs[bRow][bCol]) = b4;
        __syncthreads();
#pragma unroll
        for (int kk = 0; kk < BKK; kk++) {
            float a_reg[TM], b_reg[TN];
#pragma unroll
            for (int i = 0; i < TM; i++) a_reg[i] = As[kk][ty * TM + i];
#pragma unroll
            for (int j = 0; j < TN; j++) b_reg[j] = Bs[kk][tx * TN + j];
#pragma unroll
            for (int i = 0; i < TM; i++)
#pragma unroll
                for (int j = 0; j < TN; j++)
                    acc[i][j] += a_reg[i] * b_reg[j];
        }
        __syncthreads();
    }
#pragma unroll
    for (int i = 0; i < TM; i++) {
        int r = mBase + ty * TM + i;
        if (r >= M) continue;
#pragma unroll
        for (int j = 0; j < TN; j++) {
            int c = nBase + tx * TN + j;
            if (c >= N) continue;
            C[(size_t)r * N + c] = acc[i][j] + bias[c];
        }
    }
}

// ---------------- host ----------------
template <typename T>
static T* symaddr(const void* sym_)
{
    void* p = nullptr;
    cudaGetSymbolAddress(&p, sym_);
    return (T*)p;
}

extern "C" void kernel_launch(void* const* d_in, const int* in_sizes, int n_in,
                              void* d_out, int out_size)
{
    const float* x         = (const float*)d_in[0];
    const float* patch_w   = (const float*)d_in[1];
    const float* patch_b   = (const float*)d_in[2];
    const float* cls_token = (const float*)d_in[3];
    const float* pos_emb   = (const float*)d_in[4];
    const float* ln1_w     = (const float*)d_in[5];
    const float* ln1_b     = (const float*)d_in[6];
    const float* wq        = (const float*)d_in[7];
    const float* bq        = (const float*)d_in[8];
    const float* wk        = (const float*)d_in[9];
    const float* bk        = (const float*)d_in[10];
    const float* wv        = (const float*)d_in[11];
    const float* bv        = (const float*)d_in[12];
    const float* wy        = (const float*)d_in[13];
    const float* by        = (const float*)d_in[14];
    const float* ln2_w     = (const float*)d_in[15];
    const float* ln2_b     = (const float*)d_in[16];
    const float* mlp_w1    = (const float*)d_in[17];
    const float* mlp_b1    = (const float*)d_in[18];
    const float* mlp_w2    = (const float*)d_in[19];
    const float* mlp_b2    = (const float*)d_in[20];
    const float* head_ln_w = (const float*)d_in[21];
    const float* head_ln_b = (const float*)d_in[22];
    const float* head_w    = (const float*)d_in[23];
    const float* head_b    = (const float*)d_in[24];

    float* pe    = symaddr<float>(g_pe);
    float* h     = symaddr<float>(g_h);
    float* cls   = symaddr<float>(g_cls);
    float* clsln = symaddr<float>(g_clsln);

    __nv_bfloat16* wq_h = symaddr<__nv_bfloat16>(g_wq_h);
    __nv_bfloat16* wq_l = symaddr<__nv_bfloat16>(g_wq_l);
    __nv_bfloat16* wk_h = symaddr<__nv_bfloat16>(g_wk_h);
    __nv_bfloat16* wk_l = symaddr<__nv_bfloat16>(g_wk_l);
    __nv_bfloat16* wv_h = symaddr<__nv_bfloat16>(g_wv_h);
    __nv_bfloat16* wv_l = symaddr<__nv_bfloat16>(g_wv_l);
    __nv_bfloat16* wy_h = symaddr<__nv_bfloat16>(g_wy_h);
    __nv_bfloat16* wy_l = symaddr<__nv_bfloat16>(g_wy_l);
    __nv_bfloat16* w1_h = symaddr<__nv_bfloat16>(g_w1_h);
    __nv_bfloat16* w1_l = symaddr<__nv_bfloat16>(g_w1_l);
    __nv_bfloat16* w2_h = symaddr<__nv_bfloat16>(g_w2_h);
    __nv_bfloat16* w2_l = symaddr<__nv_bfloat16>(g_w2_l);
    __nv_bfloat16* wp_h = symaddr<__nv_bfloat16>(g_wp_h);
    __nv_bfloat16* wp_l = symaddr<__nv_bfloat16>(g_wp_l);
    __nv_bfloat16* zh   = symaddr<__nv_bfloat16>(g_zh);
    __nv_bfloat16* zl   = symaddr<__nv_bfloat16>(g_zl);
    __nv_bfloat16* yh   = symaddr<__nv_bfloat16>(g_yh);
    __nv_bfloat16* yl   = symaddr<__nv_bfloat16>(g_yl);
    __nv_bfloat16* Ah   = symaddr<__nv_bfloat16>(g_Ah);
    __nv_bfloat16* Al   = symaddr<__nv_bfloat16>(g_Al);
    __nv_bfloat16* m1h  = symaddr<__nv_bfloat16>(g_m1h);
    __nv_bfloat16* m1l  = symaddr<__nv_bfloat16>(g_m1l);
    __nv_bfloat16* qh   = symaddr<__nv_bfloat16>(g_qh);
    __nv_bfloat16* ql   = symaddr<__nv_bfloat16>(g_ql);
    __nv_bfloat16* kh   = symaddr<__nv_bfloat16>(g_kh);
    __nv_bfloat16* kl   = symaddr<__nv_bfloat16>(g_kl);
    __nv_bfloat16* vh   = symaddr<__nv_bfloat16>(g_vh);
    __nv_bfloat16* vl   = symaddr<__nv_bfloat16>(g_vl);

    cudaFuncSetAttribute(mm_gemm_k<0>, cudaFuncAttributeMaxDynamicSharedMemorySize, SMEM_MM);
    cudaFuncSetAttribute(mm_gemm_k<1>, cudaFuncAttributeMaxDynamicSharedMemorySize, SMEM_MM);
    cudaFuncSetAttribute(mm_gemm_k<3>, cudaFuncAttributeMaxDynamicSharedMemorySize, SMEM_MM);
    cudaFuncSetAttribute(mm_qkv_k,     cudaFuncAttributeMaxDynamicSharedMemorySize, SMEM_MM);
    cudaFuncSetAttribute(attn_k,       cudaFuncAttributeMaxDynamicSharedMemorySize, ATT_SMEM);

    dim3 tsb(32, 8);
    tsplit_k<<<dim3(D_ / 32, D_ / 32, L_), tsb>>>(wq, wq_h, wq_l, D_, D_);
    tsplit_k<<<dim3(D_ / 32, D_ / 32, L_), tsb>>>(wk, wk_h, wk_l, D_, D_);
    tsplit_k<<<dim3(D_ / 32, D_ / 32, L_), tsb>>>(wv, wv_h, wv_l, D_, D_);
    tsplit_k<<<dim3(D_ / 32, D_ / 32, L_), tsb>>>(wy, wy_h, wy_l, D_, D_);
    tsplit_k<<<dim3(D_ / 32, FF_ / 32, L_), tsb>>>(mlp_w1, w1_h, w1_l, D_, FF_);
    tsplit_k<<<dim3(FF_ / 32, D_ / 32, L_), tsb>>>(mlp_w2, w2_h, w2_l, FF_, D_);
    tsplit_k<<<dim3(D_ / 32, D_ / 32, 1), tsb>>>(patch_w, wp_h, wp_l, D_, D_);

    // patch embed
    patch_split_k<<<(int)(((size_t)MPAT * D_ + 255) / 256), 256>>>(x, Ah, Al);
    mm_gemm_k<0><<<dim3(D_ / TCN, MPAT / TCM), 256, SMEM_MM>>>(
        Ah, Al, wp_h, wp_l, patch_b, nullptr, pe, nullptr, nullptr, MPAT, D_, D_);
    assemble_k<<<(int)(((size_t)MTOK * D_ + 255) / 256), 256>>>(pe, cls_token, pos_emb, h);

    const int MT = (MTOK + TCM - 1) / TCM;  // 50
    for (int l = 0; l < L_; l++) {
        size_t wo  = (size_t)l * D_ * D_;
        size_t w1o = (size_t)l * D_ * FF_;
        size_t w2o = (size_t)l * FF_ * D_;

        ln_split_k<<<MTOK, 256>>>(h, ln1_w + (size_t)l * D_, ln1_b + (size_t)l * D_, zh, zl);

        mm_qkv_k<<<dim3(D_ / TCN, MT, 3), 256, SMEM_MM>>>(
            zh, zl,
            wq_h + wo, wq_l + wo, wk_h + wo, wk_l + wo, wv_h + wo, wv_l + wo,
            bq + (size_t)l * D_, bk + (size_t)l * D_, bv + (size_t)l * D_,
            qh, ql, kh, kl, vh, vl);

        attn_k<<<dim3(4, BH_), 256, ATT_SMEM>>>(qh, ql, kh, kl, vh, vl, yh, yl);

        mm_gemm_k<1><<<dim3(D_ / TCN, MT), 256, SMEM_MM>>>(
            yh, yl, wy_h + wo, wy_l + wo, by + (size_t)l * D_, h, h, nullptr, nullptr,
            MTOK, D_, D_);

        ln_split_k<<<MTOK, 256>>>(h, ln2_w + (size_t)l * D_, ln2_b + (size_t)l * D_, zh, zl);

        mm_gemm_k<3><<<dim3(FF_ / TCN, MT), 256, SMEM_MM>>>(
            zh, zl, w1_h + w1o, w1_l + w1o, mlp_b1 + (size_t)l * FF_, nullptr,
            nullptr, m1h, m1l, MTOK, FF_, D_);

        mm_gemm_k<1><<<dim3(D_ / TCN, MT), 256, SMEM_MM>>>(
            m1h, m1l, w2_h + w2o, w2_l + w2o, mlp_b2 + (size_t)l * D_, h, h,
            nullptr, nullptr, MTOK, D_, FF_);
    }

    // head
    clsgather_k<<<(B_ * D_ + 255) / 256, 256>>>(h, cls);
    ln_k<<<B_, 256>>>(cls, head_ln_w, head_ln_b, clsln);
    sgemm_head_k<<<dim3((NC_ + BN - 1) / BN, (B_ + BM - 1) / BM), 256>>>(
        clsln, head_w, head_b, (float*)d_out, B_, NC_, D_);
}